// round 12
// baseline (speedup 1.0000x reference)
#include <cuda_runtime.h>
#include <cuda_fp16.h>
#include <cstdint>
#include <math.h>

// Problem constants
static constexpr int BB = 16;     // batch
static constexpr int SS = 512;    // seq len
static constexpr int HH = 768;    // hidden
static constexpr int NHH = 12;    // heads
static constexpr int HDD = 64;    // head dim
static constexpr int MROWS = BB * SS;  // 8192

// Scratch (static device allocations allowed)
__device__ __half g_qkvh[3][(size_t)MROWS * HH];   // fp16 Q,K,V
__device__ __half g_xh[(size_t)MROWS * HH];        // fp16 hidden
__device__ __half g_wh[3][(size_t)HH * HH];        // fp16 weights

// ---------------------------------------------------------------------------
// helpers
// ---------------------------------------------------------------------------
__device__ __forceinline__ uint32_t smem_to_u32(const void* p) {
    uint32_t a;
    asm("{ .reg .u64 t; cvta.to.shared.u64 t, %1; cvt.u32.u64 %0, t; }" : "=r"(a) : "l"(p));
    return a;
}
#define CP_ASYNC16(dst_u32, src_ptr) \
    asm volatile("cp.async.cg.shared.global [%0], [%1], 16;" :: "r"(dst_u32), "l"(src_ptr) : "memory")
#define CP_COMMIT() asm volatile("cp.async.commit_group;" ::: "memory")
#define CP_WAIT(n)  asm volatile("cp.async.wait_group %0;" :: "n"(n) : "memory")

#define LDSM_X4(r0, r1, r2, r3, a) \
    asm volatile("ldmatrix.sync.aligned.m8n8.x4.shared.b16 {%0,%1,%2,%3}, [%4];" \
                 : "=r"(r0), "=r"(r1), "=r"(r2), "=r"(r3) : "r"(a))
#define LDSM_X4T(r0, r1, r2, r3, a) \
    asm volatile("ldmatrix.sync.aligned.m8n8.x4.trans.shared.b16 {%0,%1,%2,%3}, [%4];" \
                 : "=r"(r0), "=r"(r1), "=r"(r2), "=r"(r3) : "r"(a))

__device__ __forceinline__ void mma_fp16(float d[4],
                                         uint32_t a0, uint32_t a1, uint32_t a2, uint32_t a3,
                                         uint32_t b0, uint32_t b1) {
    asm volatile(
        "mma.sync.aligned.m16n8k16.row.col.f32.f16.f16.f32 "
        "{%0,%1,%2,%3}, {%4,%5,%6,%7}, {%8,%9}, {%0,%1,%2,%3};"
        : "+f"(d[0]), "+f"(d[1]), "+f"(d[2]), "+f"(d[3])
        : "r"(a0), "r"(a1), "r"(a2), "r"(a3), "r"(b0), "r"(b1));
}

// FMA-only exp (no MUFU): e^x = 2^(x*log2e)
__device__ __forceinline__ float fexp(float x) {
    float y = x * 1.4426950408889634f;
    y = fmaxf(y, -120.0f);
    float r = rintf(y);
    float f = y - r;
    float p = 1.5403530393381609e-4f;
    p = fmaf(p, f, 1.3333558146428443e-3f);
    p = fmaf(p, f, 9.6181291076284770e-3f);
    p = fmaf(p, f, 5.5504108664821580e-2f);
    p = fmaf(p, f, 2.4022650695910070e-1f);
    p = fmaf(p, f, 6.9314718055994531e-1f);
    p = fmaf(p, f, 1.0f);
    int i = (int)r;
    float s = __int_as_float((i + 127) << 23);
    return p * s;
}

// ---------------------------------------------------------------------------
// Kernel 0: fp32 -> fp16 conversion, 2 float4 per thread.
// ---------------------------------------------------------------------------
static constexpr size_t NX4 = (size_t)MROWS * HH / 4;
static constexpr size_t NW4 = (size_t)HH * HH / 4;
static constexpr size_t NTOT4 = NX4 + 3 * NW4;

__device__ __forceinline__ void split_one(
    const float* __restrict__ X,
    const float* __restrict__ Wq, const float* __restrict__ Wk, const float* __restrict__ Wv,
    size_t i)
{
    const float* src;
    __half* dst;
    size_t off;
    if (i < NX4) {
        src = X; dst = g_xh; off = i;
    } else {
        size_t j = i - NX4;
        int w = (int)(j / NW4);
        off = j - (size_t)w * NW4;
        src = (w == 0) ? Wq : (w == 1) ? Wk : Wv;
        dst = g_wh[w];
    }
    float4 v = reinterpret_cast<const float4*>(src)[off];
    __half2 h0 = __floats2half2_rn(v.x, v.y);
    __half2 h1 = __floats2half2_rn(v.z, v.w);
    uint2 st;
    st.x = reinterpret_cast<uint32_t&>(h0);
    st.y = reinterpret_cast<uint32_t&>(h1);
    *reinterpret_cast<uint2*>(dst + 4 * off) = st;
}

__global__ __launch_bounds__(256) void split_kernel(
    const float* __restrict__ X,
    const float* __restrict__ Wq, const float* __restrict__ Wk, const float* __restrict__ Wv)
{
    size_t stride = (size_t)gridDim.x * blockDim.x;
    size_t i0 = (size_t)blockIdx.x * blockDim.x + threadIdx.x;
    size_t i1 = i0 + stride;
    if (i0 < NTOT4) split_one(X, Wq, Wk, Wv, i0);
    if (i1 < NTOT4) split_one(X, Wq, Wk, Wv, i1);
}

// ---------------------------------------------------------------------------
// Kernel 1: QKV projection, fp16 mma.sync + ldmatrix.
// NOW: block tile 128x256, 8 warps (2m x 4n), warp tile 64x64 (32 MMAs per
// LDSM group). BK=64, 3-stage ring, prefetch distance 1, 1 barrier/iter.
// grid = (3, 64, 3) = 576 CTAs, 1 CTA/SM (166KB smem).
// ---------------------------------------------------------------------------
static constexpr int BK = 64;
static constexpr int KSTRIDE = 72;                        // fp16 per smem row
static constexpr int A_TILE_BYTES = 128 * KSTRIDE * 2;    // 18432
static constexpr int B_TILE_BYTES2 = 256 * KSTRIDE * 2;   // 36864
static constexpr int STAGE_BYTES = A_TILE_BYTES + B_TILE_BYTES2;   // 55296
static constexpr int GEMM_SMEM_TOTAL = 3 * STAGE_BYTES;   // 165888
static constexpr int NKT = HH / BK;                       // 12

__device__ __forceinline__ void load_stage_async(
    char* smem, int s,
    const __half* __restrict__ A, const __half* __restrict__ B,
    int k0, int tid)
{
    char* base = smem + s * STAGE_BYTES;
    // A: 128 rows x 8 quads = 1024 copies; B: 256 rows x 8 quads = 2048 copies
    #pragma unroll
    for (int e = 0; e < 4; e++) {
        int idx = (e << 8) + tid;            // 0..1023
        int r = idx >> 3;                    // 0..127
        int q = idx & 7;
        CP_ASYNC16(smem_to_u32(base + (r * KSTRIDE + q * 8) * 2),
                   A + (size_t)r * HH + k0 + q * 8);
    }
    #pragma unroll
    for (int e = 0; e < 8; e++) {
        int idx = (e << 8) + tid;            // 0..2047
        int r = idx >> 3;                    // 0..255
        int q = idx & 7;
        CP_ASYNC16(smem_to_u32(base + A_TILE_BYTES + (r * KSTRIDE + q * 8) * 2),
                   B + (size_t)r * HH + k0 + q * 8);
    }
}

__global__ __launch_bounds__(256, 1) void qkv_gemm_mma(
    const float* __restrict__ bq, const float* __restrict__ bk, const float* __restrict__ bv)
{
    extern __shared__ char smem[];
    const uint32_t smem_base = smem_to_u32(smem);
    const int tid = threadIdx.x;
    const int wid = tid >> 5;
    const int lane = tid & 31;
    const int g = lane >> 2;
    const int tig = lane & 3;

    const int which = blockIdx.z;
    const int n0 = blockIdx.x * 256;
    const int m0 = blockIdx.y * 128;
    const float* bias = (which == 0) ? bq : (which == 1) ? bk : bv;
    __half* out = g_qkvh[which];

    const __half* A = g_xh + (size_t)m0 * HH;
    const __half* B = g_wh[which] + (size_t)n0 * HH;

    const int m_w = (wid & 1) * 64;    // warp m offset (2 warps over 128)
    const int n_w = (wid >> 1) * 64;   // warp n offset (4 warps over 256)

    const uint32_t aoff = ((m_w + (lane & 15)) * KSTRIDE + (lane >> 4) * 8) * 2;
    const uint32_t boff = ((n_w + ((lane >> 4) & 1) * 8 + (lane & 7)) * KSTRIDE
                           + ((lane >> 3) & 1) * 8) * 2;

    float acc[4][8][4];
    #pragma unroll
    for (int i = 0; i < 4; i++)
        #pragma unroll
        for (int j = 0; j < 8; j++)
            #pragma unroll
            for (int r = 0; r < 4; r++) acc[i][j][r] = 0.0f;

    load_stage_async(smem, 0, A, B, 0, tid);
    CP_COMMIT();

    for (int kt = 0; kt < NKT; kt++) {
        const int s = kt % 3;
        if (kt + 1 < NKT) {
            load_stage_async(smem, (kt + 1) % 3, A, B, (kt + 1) * BK, tid);
            CP_COMMIT();
            CP_WAIT(1);
        } else {
            CP_WAIT(0);
        }
        __syncthreads();
        // single barrier per iter: 3-stage ring, prefetch distance 1 —
        // writer at iter kt+1 targets stage (kt+2)%3; slowest reader (past
        // barrier kt) reads stage kt%3; distances 1,2 mod 3 — no aliasing.

        const uint32_t sA = smem_base + s * STAGE_BYTES;
        const uint32_t sB = sA + A_TILE_BYTES;

        #pragma unroll
        for (int kc = 0; kc < 4; kc++) {
            uint32_t a[4][4];
            #pragma unroll
            for (int mi = 0; mi < 4; mi++)
                LDSM_X4(a[mi][0], a[mi][1], a[mi][2], a[mi][3],
                        sA + aoff + mi * 16 * KSTRIDE * 2 + kc * 32);
            uint32_t b[4][4];
            #pragma unroll
            for (int n16 = 0; n16 < 4; n16++)
                LDSM_X4(b[n16][0], b[n16][1], b[n16][2], b[n16][3],
                        sB + boff + n16 * 16 * KSTRIDE * 2 + kc * 32);
            #pragma unroll
            for (int mi = 0; mi < 4; mi++)
                #pragma unroll
                for (int n16 = 0; n16 < 4; n16++) {
                    mma_fp16(acc[mi][n16 * 2],     a[mi][0], a[mi][1], a[mi][2], a[mi][3],
                             b[n16][0], b[n16][1]);
                    mma_fp16(acc[mi][n16 * 2 + 1], a[mi][0], a[mi][1], a[mi][2], a[mi][3],
                             b[n16][2], b[n16][3]);
                }
        }
    }

    // epilogue: fp32 acc + bias -> fp16 (half2 stores)
    #pragma unroll
    for (int mi = 0; mi < 4; mi++) {
        int row = m0 + m_w + mi * 16 + g;
        #pragma unroll
        for (int nj = 0; nj < 8; nj++) {
            int n = n0 + n_w + nj * 8 + tig * 2;
            float b0f = bias[n], b1f = bias[n + 1];
            __half2 v0 = __floats2half2_rn(acc[mi][nj][0] + b0f, acc[mi][nj][1] + b1f);
            __half2 v1 = __floats2half2_rn(acc[mi][nj][2] + b0f, acc[mi][nj][3] + b1f);
            *reinterpret_cast<__half2*>(out + (size_t)row * HH + n) = v0;
            *reinterpret_cast<__half2*>(out + (size_t)(row + 8) * HH + n) = v1;
        }
    }
}

// ---------------------------------------------------------------------------
// Kernel 2: register-resident flash-style attention (unchanged from round 11).
// ---------------------------------------------------------------------------
static constexpr int TST = 72;
static constexpr int TILE_B = 64 * TST * 2;

static constexpr int SM_Q    = 0;
static constexpr int SM_K    = SM_Q + TILE_B;
static constexpr int SM_V    = SM_K + 8 * TILE_B;
static constexpr int SM_MSK  = SM_V + 8 * TILE_B;
static constexpr int SM_WMAX = SM_MSK + SS * 4;
static constexpr int SM_WSUM = SM_WMAX + 4 * 64 * 4;
static constexpr int ATTN_SMEM_TOTAL = SM_WSUM + 4 * 64 * 4;
static constexpr int CTXST = 68;

__global__ __launch_bounds__(512, 1) void attn_kernel(
    const float* __restrict__ mask,
    float* __restrict__ ctx,
    float* __restrict__ probs)
{
    extern __shared__ char smem[];
    const uint32_t smem_base = smem_to_u32(smem);
    float* msk   = (float*)(smem + SM_MSK);
    float* wmax  = (float*)(smem + SM_WMAX);
    float* wsum  = (float*)(smem + SM_WSUM);
    float* ctxb  = (float*)(smem + SM_K);     // aliases K region

    const int qt = blockIdx.x;
    const int h  = blockIdx.y;
    const int b  = blockIdx.z;
    const int tid  = threadIdx.x;
    const int lane = tid & 31;
    const int g    = lane >> 2;
    const int tig  = lane & 3;
    const int mw   = ((tid >> 5) & 3);
    const int nw   = (tid >> 7);
    const int q0 = qt * 64;
    const float scale = 0.125f;

    const __half* Q = g_qkvh[0];
    const __half* K = g_qkvh[1];
    const __half* V = g_qkvh[2];

    msk[tid] = (1.0f - mask[(size_t)b * SS + tid]) * -10000.0f;

    const int r = tid >> 3, q = tid & 7;

    {
        uint4 v = *reinterpret_cast<const uint4*>(
            Q + ((size_t)(b * SS + q0 + r)) * HH + h * HDD + q * 8);
        *reinterpret_cast<uint4*>((__half*)(smem + SM_Q) + r * TST + q * 8) = v;
    }
    // K commits: tile0, tile1, {2,3}, {4,5}, {6,7}; V -> 1 group
    #pragma unroll
    for (int kt = 0; kt < 8; kt++) {
        CP_ASYNC16(smem_base + SM_K + kt * TILE_B + r * TST * 2 + q * 16,
                   K + ((size_t)(b * SS + kt * 64 + r)) * HH + h * HDD + q * 8);
        if (kt == 0 || kt == 1 || kt == 3 || kt == 5 || kt == 7) CP_COMMIT();
    }
    #pragma unroll
    for (int kt = 0; kt < 8; kt++) {
        CP_ASYNC16(smem_base + SM_V + kt * TILE_B + r * TST * 2 + q * 16,
                   V + ((size_t)(b * SS + kt * 64 + r)) * HH + h * HDD + q * 8);
    }
    CP_COMMIT();

    const uint32_t koff = (nw * 16 + ((lane >> 4) & 1) * 8 + (lane & 7)) * TST * 2
                          + ((lane >> 3) & 1) * 16;
    const uint32_t voff = (nw * 16 + (lane & 7) + ((lane >> 3) & 1) * 8) * TST * 2
                          + ((lane >> 4) & 1) * 16;

    CP_WAIT(5);
    __syncthreads();

    uint32_t qf[4][4];
    {
        const uint32_t qbase = smem_base + SM_Q
            + ((mw * 16 + (lane & 15)) * TST) * 2 + (lane >> 4) * 16;
        #pragma unroll
        for (int kc = 0; kc < 4; kc++)
            LDSM_X4(qf[kc][0], qf[kc][1], qf[kc][2], qf[kc][3], qbase + kc * 32);
    }

    float sreg[8][2][4];
    #pragma unroll
    for (int kt = 0; kt < 8; kt++) {
        if (kt == 1)      { CP_WAIT(4); __syncthreads(); }
        else if (kt == 2) { CP_WAIT(3); __syncthreads(); }
        else if (kt == 4) { CP_WAIT(2); __syncthreads(); }
        else if (kt == 6) { CP_WAIT(1); __syncthreads(); }

        const uint32_t kvb = smem_base + SM_K + kt * TILE_B;
        float acc[2][4];
        #pragma unroll
        for (int ni = 0; ni < 2; ni++)
            #pragma unroll
            for (int rr = 0; rr < 4; rr++) acc[ni][rr] = 0.0f;

        #pragma unroll
        for (int kc = 0; kc < 4; kc++) {
            uint32_t bf[4];
            LDSM_X4(bf[0], bf[1], bf[2], bf[3], kvb + koff + kc * 32);
            mma_fp16(acc[0], qf[kc][0], qf[kc][1], qf[kc][2], qf[kc][3], bf[0], bf[1]);
            mma_fp16(acc[1], qf[kc][0], qf[kc][1], qf[kc][2], qf[kc][3], bf[2], bf[3]);
        }
        #pragma unroll
        for (int ni = 0; ni < 2; ni++) {
            int col = kt * 64 + nw * 16 + ni * 8 + tig * 2;
            sreg[kt][ni][0] = acc[ni][0] * scale + msk[col];
            sreg[kt][ni][1] = acc[ni][1] * scale + msk[col + 1];
            sreg[kt][ni][2] = acc[ni][2] * scale + msk[col];
            sreg[kt][ni][3] = acc[ni][3] * scale + msk[col + 1];
        }
    }

    const int r0 = mw * 16 + g;
    const int r1 = r0 + 8;

    float m0 = -1e30f, m1 = -1e30f;
    #pragma unroll
    for (int kt = 0; kt < 8; kt++)
        #pragma unroll
        for (int ni = 0; ni < 2; ni++) {
            m0 = fmaxf(m0, fmaxf(sreg[kt][ni][0], sreg[kt][ni][1]));
            m1 = fmaxf(m1, fmaxf(sreg[kt][ni][2], sreg[kt][ni][3]));
        }
    #pragma unroll
    for (int o = 1; o <= 2; o <<= 1) {
        m0 = fmaxf(m0, __shfl_xor_sync(0xffffffffu, m0, o));
        m1 = fmaxf(m1, __shfl_xor_sync(0xffffffffu, m1, o));
    }
    if (tig == 0) {
        wmax[nw * 64 + r0] = m0;
        wmax[nw * 64 + r1] = m1;
    }
    __syncthreads();
    float rm0 = fmaxf(fmaxf(wmax[r0], wmax[64 + r0]), fmaxf(wmax[128 + r0], wmax[192 + r0]));
    float rm1 = fmaxf(fmaxf(wmax[r1], wmax[64 + r1]), fmaxf(wmax[128 + r1], wmax[192 + r1]));

    float s0 = 0.0f, s1 = 0.0f;
    #pragma unroll
    for (int kt = 0; kt < 8; kt++)
        #pragma unroll
        for (int ni = 0; ni < 2; ni++) {
            float e0 = fexp(sreg[kt][ni][0] - rm0);
            float e1 = fexp(sreg[kt][ni][1] - rm0);
            float e2 = fexp(sreg[kt][ni][2] - rm1);
            float e3 = fexp(sreg[kt][ni][3] - rm1);
            sreg[kt][ni][0] = e0; sreg[kt][ni][1] = e1;
            sreg[kt][ni][2] = e2; sreg[kt][ni][3] = e3;
            s0 += e0 + e1;
            s1 += e2 + e3;
        }
    #pragma unroll
    for (int o = 1; o <= 2; o <<= 1) {
        s0 += __shfl_xor_sync(0xffffffffu, s0, o);
        s1 += __shfl_xor_sync(0xffffffffu, s1, o);
    }
    if (tig == 0) {
        wsum[nw * 64 + r0] = s0;
        wsum[nw * 64 + r1] = s1;
    }
    CP_WAIT(0);
    __syncthreads();
    float inv0 = 1.0f / (wsum[r0] + wsum[64 + r0] + wsum[128 + r0] + wsum[192 + r0]);
    float inv1 = 1.0f / (wsum[r1] + wsum[64 + r1] + wsum[128 + r1] + wsum[192 + r1]);

    const size_t pb0 = (((size_t)b * NHH + h) * SS + q0 + r0) * SS;
    const size_t pb1 = (((size_t)b * NHH + h) * SS + q0 + r1) * SS;

    float cacc[8][4];
    #pragma unroll
    for (int nd = 0; nd < 8; nd++)
        #pragma unroll
        for (int rr = 0; rr < 4; rr++) cacc[nd][rr] = 0.0f;

    #pragma unroll
    for (int kt = 0; kt < 8; kt++) {
        uint32_t paf[4];
        #pragma unroll
        for (int ni = 0; ni < 2; ni++) {
            int col = kt * 64 + nw * 16 + ni * 8 + tig * 2;
            float p0 = sreg[kt][ni][0] * inv0;
            float p1 = sreg[kt][ni][1] * inv0;
            float p2 = sreg[kt][ni][2] * inv1;
            float p3 = sreg[kt][ni][3] * inv1;
            __stcs(reinterpret_cast<float2*>(probs + pb0 + col), make_float2(p0, p1));
            __stcs(reinterpret_cast<float2*>(probs + pb1 + col), make_float2(p2, p3));
            __half2 h01 = __floats2half2_rn(p0, p1);
            __half2 h23 = __floats2half2_rn(p2, p3);
            paf[ni * 2]     = reinterpret_cast<uint32_t&>(h01);
            paf[ni * 2 + 1] = reinterpret_cast<uint32_t&>(h23);
        }
        const uint32_t kvb = smem_base + SM_V + kt * TILE_B;
        #pragma unroll
        for (int dd = 0; dd < 4; dd++) {
            uint32_t bf[4];
            LDSM_X4T(bf[0], bf[1], bf[2], bf[3], kvb + voff + dd * 32);
            mma_fp16(cacc[dd * 2],     paf[0], paf[1], paf[2], paf[3], bf[0], bf[1]);
            mma_fp16(cacc[dd * 2 + 1], paf[0], paf[1], paf[2], paf[3], bf[2], bf[3]);
        }
    }

    #pragma unroll
    for (int nd = 0; nd < 8; nd++) {
        int d = nd * 8 + tig * 2;
        *reinterpret_cast<float2*>(ctxb + (nw * 64 + r0) * CTXST + d) =
            make_float2(cacc[nd][0], cacc[nd][1]);
        *reinterpret_cast<float2*>(ctxb + (nw * 64 + r1) * CTXST + d) =
            make_float2(cacc[nd][2], cacc[nd][3]);
    }
    __syncthreads();

    {
        int row = tid >> 3;
        int d0  = (tid & 7) * 8;
        #pragma unroll
        for (int half = 0; half < 2; half++) {
            int d = d0 + half * 4;
            float4 v0 = *reinterpret_cast<float4*>(ctxb + (0 * 64 + row) * CTXST + d);
            float4 v1 = *reinterpret_cast<float4*>(ctxb + (1 * 64 + row) * CTXST + d);
            float4 v2 = *reinterpret_cast<float4*>(ctxb + (2 * 64 + row) * CTXST + d);
            float4 v3 = *reinterpret_cast<float4*>(ctxb + (3 * 64 + row) * CTXST + d);
            float4 o;
            o.x = v0.x + v1.x + v2.x + v3.x;
            o.y = v0.y + v1.y + v2.y + v3.y;
            o.z = v0.z + v1.z + v2.z + v3.z;
            o.w = v0.w + v1.w + v2.w + v3.w;
            *reinterpret_cast<float4*>(
                ctx + ((size_t)(b * SS + q0 + row)) * HH + h * HDD + d) = o;
        }
    }
}

// ---------------------------------------------------------------------------
// kernel_launch
// ---------------------------------------------------------------------------
extern "C" void kernel_launch(void* const* d_in, const int* in_sizes, int n_in,
                              void* d_out, int out_size)
{
    const float* hidden = (const float*)d_in[0];
    const float* mask   = (const float*)d_in[1];
    const float* Wq = (const float*)d_in[2];
    const float* bq = (const float*)d_in[3];
    const float* Wk = (const float*)d_in[4];
    const float* bk = (const float*)d_in[5];
    const float* Wv = (const float*)d_in[6];
    const float* bv = (const float*)d_in[7];

    float* out   = (float*)d_out;
    float* ctx   = out;
    float* probs = out + (size_t)BB * SS * HH;

    // 0) fp32 -> fp16
    int nblk = (int)((NTOT4 / 2 + 255) / 256);
    split_kernel<<<nblk, 256>>>(hidden, Wq, Wk, Wv);

    // 1) QKV projections (fp16 mma.sync, 128x256 block, 64x64 warp tiles)
    cudaFuncSetAttribute(qkv_gemm_mma, cudaFuncAttributeMaxDynamicSharedMemorySize, GEMM_SMEM_TOTAL);
    dim3 g1(HH / 256, MROWS / 128, 3);
    qkv_gemm_mma<<<g1, 256, GEMM_SMEM_TOTAL>>>(bq, bk, bv);

    // 2) fused attention (register-resident, full K/V preload)
    cudaFuncSetAttribute(attn_kernel, cudaFuncAttributeMaxDynamicSharedMemorySize, ATTN_SMEM_TOTAL);
    dim3 g2(SS / 64, NHH, BB);
    attn_kernel<<<g2, 512, ATTN_SMEM_TOTAL>>>(mask, ctx, probs);
}

// round 13
// speedup vs baseline: 1.0183x; 1.0183x over previous
#include <cuda_runtime.h>
#include <cuda_fp16.h>
#include <cstdint>
#include <math.h>

// Problem constants
static constexpr int BB = 16;     // batch
static constexpr int SS = 512;    // seq len
static constexpr int HH = 768;    // hidden
static constexpr int NHH = 12;    // heads
static constexpr int HDD = 64;    // head dim
static constexpr int MROWS = BB * SS;  // 8192

// Scratch (static device allocations allowed)
__device__ __half g_qkvh[3][(size_t)MROWS * HH];   // fp16 Q,K,V
__device__ __half g_xh[(size_t)MROWS * HH];        // fp16 hidden
__device__ __half g_wh[3][(size_t)HH * HH];        // fp16 weights

// ---------------------------------------------------------------------------
// helpers
// ---------------------------------------------------------------------------
__device__ __forceinline__ uint32_t smem_to_u32(const void* p) {
    uint32_t a;
    asm("{ .reg .u64 t; cvta.to.shared.u64 t, %1; cvt.u32.u64 %0, t; }" : "=r"(a) : "l"(p));
    return a;
}
#define CP_ASYNC16(dst_u32, src_ptr) \
    asm volatile("cp.async.cg.shared.global [%0], [%1], 16;" :: "r"(dst_u32), "l"(src_ptr) : "memory")
#define CP_COMMIT() asm volatile("cp.async.commit_group;" ::: "memory")
#define CP_WAIT(n)  asm volatile("cp.async.wait_group %0;" :: "n"(n) : "memory")

#define LDSM_X4(r0, r1, r2, r3, a) \
    asm volatile("ldmatrix.sync.aligned.m8n8.x4.shared.b16 {%0,%1,%2,%3}, [%4];" \
                 : "=r"(r0), "=r"(r1), "=r"(r2), "=r"(r3) : "r"(a))
#define LDSM_X4T(r0, r1, r2, r3, a) \
    asm volatile("ldmatrix.sync.aligned.m8n8.x4.trans.shared.b16 {%0,%1,%2,%3}, [%4];" \
                 : "=r"(r0), "=r"(r1), "=r"(r2), "=r"(r3) : "r"(a))

__device__ __forceinline__ void mma_fp16(float d[4],
                                         uint32_t a0, uint32_t a1, uint32_t a2, uint32_t a3,
                                         uint32_t b0, uint32_t b1) {
    asm volatile(
        "mma.sync.aligned.m16n8k16.row.col.f32.f16.f16.f32 "
        "{%0,%1,%2,%3}, {%4,%5,%6,%7}, {%8,%9}, {%0,%1,%2,%3};"
        : "+f"(d[0]), "+f"(d[1]), "+f"(d[2]), "+f"(d[3])
        : "r"(a0), "r"(a1), "r"(a2), "r"(a3), "r"(b0), "r"(b1));
}

// FMA-only exp (no MUFU): e^x = 2^(x*log2e)
__device__ __forceinline__ float fexp(float x) {
    float y = x * 1.4426950408889634f;
    y = fmaxf(y, -120.0f);
    float r = rintf(y);
    float f = y - r;
    float p = 1.5403530393381609e-4f;
    p = fmaf(p, f, 1.3333558146428443e-3f);
    p = fmaf(p, f, 9.6181291076284770e-3f);
    p = fmaf(p, f, 5.5504108664821580e-2f);
    p = fmaf(p, f, 2.4022650695910070e-1f);
    p = fmaf(p, f, 6.9314718055994531e-1f);
    p = fmaf(p, f, 1.0f);
    int i = (int)r;
    float s = __int_as_float((i + 127) << 23);
    return p * s;
}

// ---------------------------------------------------------------------------
// Kernel 0: fp32 -> fp16 conversion, 2 float4 per thread.
// ---------------------------------------------------------------------------
static constexpr size_t NX4 = (size_t)MROWS * HH / 4;
static constexpr size_t NW4 = (size_t)HH * HH / 4;
static constexpr size_t NTOT4 = NX4 + 3 * NW4;

__device__ __forceinline__ void split_one(
    const float* __restrict__ X,
    const float* __restrict__ Wq, const float* __restrict__ Wk, const float* __restrict__ Wv,
    size_t i)
{
    const float* src;
    __half* dst;
    size_t off;
    if (i < NX4) {
        src = X; dst = g_xh; off = i;
    } else {
        size_t j = i - NX4;
        int w = (int)(j / NW4);
        off = j - (size_t)w * NW4;
        src = (w == 0) ? Wq : (w == 1) ? Wk : Wv;
        dst = g_wh[w];
    }
    float4 v = reinterpret_cast<const float4*>(src)[off];
    __half2 h0 = __floats2half2_rn(v.x, v.y);
    __half2 h1 = __floats2half2_rn(v.z, v.w);
    uint2 st;
    st.x = reinterpret_cast<uint32_t&>(h0);
    st.y = reinterpret_cast<uint32_t&>(h1);
    *reinterpret_cast<uint2*>(dst + 4 * off) = st;
}

__global__ __launch_bounds__(256) void split_kernel(
    const float* __restrict__ X,
    const float* __restrict__ Wq, const float* __restrict__ Wk, const float* __restrict__ Wv)
{
    size_t stride = (size_t)gridDim.x * blockDim.x;
    size_t i0 = (size_t)blockIdx.x * blockDim.x + threadIdx.x;
    size_t i1 = i0 + stride;
    if (i0 < NTOT4) split_one(X, Wq, Wk, Wv, i0);
    if (i1 < NTOT4) split_one(X, Wq, Wk, Wv, i1);
}

// ---------------------------------------------------------------------------
// Kernel 1: QKV projection, fp16 mma.sync + ldmatrix.
// NOW: block tile 128x256 with 512 THREADS = 16 warps (2m x 8n), warp tile
// 64x32 (identical fragment math to round 11). BK=64, 3-stage ring,
// prefetch distance 1, 1 barrier/iter. grid = (3, 64, 3), 1 CTA/SM, 16 warps/SM.
// ---------------------------------------------------------------------------
static constexpr int BK = 64;
static constexpr int KSTRIDE = 72;                        // fp16 per smem row
static constexpr int A_TILE_BYTES = 128 * KSTRIDE * 2;    // 18432
static constexpr int B_TILE_BYTES2 = 256 * KSTRIDE * 2;   // 36864
static constexpr int STAGE_BYTES = A_TILE_BYTES + B_TILE_BYTES2;   // 55296
static constexpr int GEMM_SMEM_TOTAL = 3 * STAGE_BYTES;   // 165888
static constexpr int NKT = HH / BK;                       // 12

__device__ __forceinline__ void load_stage_async(
    char* smem, int s,
    const __half* __restrict__ A, const __half* __restrict__ B,
    int k0, int tid)
{
    char* base = smem + s * STAGE_BYTES;
    // A: 128 rows x 8 quads = 1024 copies (2 iters of 512 threads)
    #pragma unroll
    for (int e = 0; e < 2; e++) {
        int idx = (e << 9) + tid;            // 0..1023
        int r = idx >> 3;                    // 0..127
        int q = idx & 7;
        CP_ASYNC16(smem_to_u32(base + (r * KSTRIDE + q * 8) * 2),
                   A + (size_t)r * HH + k0 + q * 8);
    }
    // B: 256 rows x 8 quads = 2048 copies (4 iters of 512 threads)
    #pragma unroll
    for (int e = 0; e < 4; e++) {
        int idx = (e << 9) + tid;            // 0..2047
        int r = idx >> 3;                    // 0..255
        int q = idx & 7;
        CP_ASYNC16(smem_to_u32(base + A_TILE_BYTES + (r * KSTRIDE + q * 8) * 2),
                   B + (size_t)r * HH + k0 + q * 8);
    }
}

__global__ __launch_bounds__(512, 1) void qkv_gemm_mma(
    const float* __restrict__ bq, const float* __restrict__ bk, const float* __restrict__ bv)
{
    extern __shared__ char smem[];
    const uint32_t smem_base = smem_to_u32(smem);
    const int tid = threadIdx.x;
    const int wid = tid >> 5;    // 0..15
    const int lane = tid & 31;
    const int g = lane >> 2;
    const int tig = lane & 3;

    const int which = blockIdx.z;
    const int n0 = blockIdx.x * 256;
    const int m0 = blockIdx.y * 128;
    const float* bias = (which == 0) ? bq : (which == 1) ? bk : bv;
    __half* out = g_qkvh[which];

    const __half* A = g_xh + (size_t)m0 * HH;
    const __half* B = g_wh[which] + (size_t)n0 * HH;

    const int m_w = (wid & 1) * 64;    // 2 warps over 128 m
    const int n_w = (wid >> 1) * 32;   // 8 warps over 256 n

    const uint32_t aoff = ((m_w + (lane & 15)) * KSTRIDE + (lane >> 4) * 8) * 2;
    const uint32_t boff = ((n_w + ((lane >> 4) & 1) * 8 + (lane & 7)) * KSTRIDE
                           + ((lane >> 3) & 1) * 8) * 2;

    float acc[4][4][4];
    #pragma unroll
    for (int i = 0; i < 4; i++)
        #pragma unroll
        for (int j = 0; j < 4; j++)
            #pragma unroll
            for (int r = 0; r < 4; r++) acc[i][j][r] = 0.0f;

    load_stage_async(smem, 0, A, B, 0, tid);
    CP_COMMIT();

    for (int kt = 0; kt < NKT; kt++) {
        const int s = kt % 3;
        if (kt + 1 < NKT) {
            load_stage_async(smem, (kt + 1) % 3, A, B, (kt + 1) * BK, tid);
            CP_COMMIT();
            CP_WAIT(1);
        } else {
            CP_WAIT(0);
        }
        __syncthreads();
        // single barrier per iter: 3-stage ring, prefetch distance 1 —
        // writer at iter kt+1 targets stage (kt+2)%3; slowest reader (past
        // barrier kt) reads stage kt%3; distances 1,2 mod 3 — no aliasing.

        const uint32_t sA = smem_base + s * STAGE_BYTES;
        const uint32_t sB = sA + A_TILE_BYTES;

        #pragma unroll
        for (int kc = 0; kc < 4; kc++) {
            uint32_t a[4][4];
            #pragma unroll
            for (int mi = 0; mi < 4; mi++)
                LDSM_X4(a[mi][0], a[mi][1], a[mi][2], a[mi][3],
                        sA + aoff + mi * 16 * KSTRIDE * 2 + kc * 32);
            uint32_t b[2][4];
            #pragma unroll
            for (int n2 = 0; n2 < 2; n2++)
                LDSM_X4(b[n2][0], b[n2][1], b[n2][2], b[n2][3],
                        sB + boff + n2 * 16 * KSTRIDE * 2 + kc * 32);
            #pragma unroll
            for (int mi = 0; mi < 4; mi++)
                #pragma unroll
                for (int ni = 0; ni < 4; ni++)
                    mma_fp16(acc[mi][ni], a[mi][0], a[mi][1], a[mi][2], a[mi][3],
                             b[ni >> 1][(ni & 1) * 2], b[ni >> 1][(ni & 1) * 2 + 1]);
        }
    }

    // epilogue: fp32 acc + bias -> fp16 (half2 stores)
    #pragma unroll
    for (int mi = 0; mi < 4; mi++) {
        int row = m0 + m_w + mi * 16 + g;
        #pragma unroll
        for (int ni = 0; ni < 4; ni++) {
            int n = n0 + n_w + ni * 8 + tig * 2;
            float b0f = bias[n], b1f = bias[n + 1];
            __half2 v0 = __floats2half2_rn(acc[mi][ni][0] + b0f, acc[mi][ni][1] + b1f);
            __half2 v1 = __floats2half2_rn(acc[mi][ni][2] + b0f, acc[mi][ni][3] + b1f);
            *reinterpret_cast<__half2*>(out + (size_t)row * HH + n) = v0;
            *reinterpret_cast<__half2*>(out + (size_t)(row + 8) * HH + n) = v1;
        }
    }
}

// ---------------------------------------------------------------------------
// Kernel 2: register-resident flash-style attention (unchanged).
// ---------------------------------------------------------------------------
static constexpr int TST = 72;
static constexpr int TILE_B = 64 * TST * 2;

static constexpr int SM_Q    = 0;
static constexpr int SM_K    = SM_Q + TILE_B;
static constexpr int SM_V    = SM_K + 8 * TILE_B;
static constexpr int SM_MSK  = SM_V + 8 * TILE_B;
static constexpr int SM_WMAX = SM_MSK + SS * 4;
static constexpr int SM_WSUM = SM_WMAX + 4 * 64 * 4;
static constexpr int ATTN_SMEM_TOTAL = SM_WSUM + 4 * 64 * 4;
static constexpr int CTXST = 68;

__global__ __launch_bounds__(512, 1) void attn_kernel(
    const float* __restrict__ mask,
    float* __restrict__ ctx,
    float* __restrict__ probs)
{
    extern __shared__ char smem[];
    const uint32_t smem_base = smem_to_u32(smem);
    float* msk   = (float*)(smem + SM_MSK);
    float* wmax  = (float*)(smem + SM_WMAX);
    float* wsum  = (float*)(smem + SM_WSUM);
    float* ctxb  = (float*)(smem + SM_K);     // aliases K region

    const int qt = blockIdx.x;
    const int h  = blockIdx.y;
    const int b  = blockIdx.z;
    const int tid  = threadIdx.x;
    const int lane = tid & 31;
    const int g    = lane >> 2;
    const int tig  = lane & 3;
    const int mw   = ((tid >> 5) & 3);
    const int nw   = (tid >> 7);
    const int q0 = qt * 64;
    const float scale = 0.125f;

    const __half* Q = g_qkvh[0];
    const __half* K = g_qkvh[1];
    const __half* V = g_qkvh[2];

    msk[tid] = (1.0f - mask[(size_t)b * SS + tid]) * -10000.0f;

    const int r = tid >> 3, q = tid & 7;

    {
        uint4 v = *reinterpret_cast<const uint4*>(
            Q + ((size_t)(b * SS + q0 + r)) * HH + h * HDD + q * 8);
        *reinterpret_cast<uint4*>((__half*)(smem + SM_Q) + r * TST + q * 8) = v;
    }
    // K commits: tile0, tile1, {2,3}, {4,5}, {6,7}; V -> 1 group
    #pragma unroll
    for (int kt = 0; kt < 8; kt++) {
        CP_ASYNC16(smem_base + SM_K + kt * TILE_B + r * TST * 2 + q * 16,
                   K + ((size_t)(b * SS + kt * 64 + r)) * HH + h * HDD + q * 8);
        if (kt == 0 || kt == 1 || kt == 3 || kt == 5 || kt == 7) CP_COMMIT();
    }
    #pragma unroll
    for (int kt = 0; kt < 8; kt++) {
        CP_ASYNC16(smem_base + SM_V + kt * TILE_B + r * TST * 2 + q * 16,
                   V + ((size_t)(b * SS + kt * 64 + r)) * HH + h * HDD + q * 8);
    }
    CP_COMMIT();

    const uint32_t koff = (nw * 16 + ((lane >> 4) & 1) * 8 + (lane & 7)) * TST * 2
                          + ((lane >> 3) & 1) * 16;
    const uint32_t voff = (nw * 16 + (lane & 7) + ((lane >> 3) & 1) * 8) * TST * 2
                          + ((lane >> 4) & 1) * 16;

    CP_WAIT(5);
    __syncthreads();

    uint32_t qf[4][4];
    {
        const uint32_t qbase = smem_base + SM_Q
            + ((mw * 16 + (lane & 15)) * TST) * 2 + (lane >> 4) * 16;
        #pragma unroll
        for (int kc = 0; kc < 4; kc++)
            LDSM_X4(qf[kc][0], qf[kc][1], qf[kc][2], qf[kc][3], qbase + kc * 32);
    }

    float sreg[8][2][4];
    #pragma unroll
    for (int kt = 0; kt < 8; kt++) {
        if (kt == 1)      { CP_WAIT(4); __syncthreads(); }
        else if (kt == 2) { CP_WAIT(3); __syncthreads(); }
        else if (kt == 4) { CP_WAIT(2); __syncthreads(); }
        else if (kt == 6) { CP_WAIT(1); __syncthreads(); }

        const uint32_t kvb = smem_base + SM_K + kt * TILE_B;
        float acc[2][4];
        #pragma unroll
        for (int ni = 0; ni < 2; ni++)
            #pragma unroll
            for (int rr = 0; rr < 4; rr++) acc[ni][rr] = 0.0f;

        #pragma unroll
        for (int kc = 0; kc < 4; kc++) {
            uint32_t bf[4];
            LDSM_X4(bf[0], bf[1], bf[2], bf[3], kvb + koff + kc * 32);
            mma_fp16(acc[0], qf[kc][0], qf[kc][1], qf[kc][2], qf[kc][3], bf[0], bf[1]);
            mma_fp16(acc[1], qf[kc][0], qf[kc][1], qf[kc][2], qf[kc][3], bf[2], bf[3]);
        }
        #pragma unroll
        for (int ni = 0; ni < 2; ni++) {
            int col = kt * 64 + nw * 16 + ni * 8 + tig * 2;
            sreg[kt][ni][0] = acc[ni][0] * scale + msk[col];
            sreg[kt][ni][1] = acc[ni][1] * scale + msk[col + 1];
            sreg[kt][ni][2] = acc[ni][2] * scale + msk[col];
            sreg[kt][ni][3] = acc[ni][3] * scale + msk[col + 1];
        }
    }

    const int r0 = mw * 16 + g;
    const int r1 = r0 + 8;

    float m0 = -1e30f, m1 = -1e30f;
    #pragma unroll
    for (int kt = 0; kt < 8; kt++)
        #pragma unroll
        for (int ni = 0; ni < 2; ni++) {
            m0 = fmaxf(m0, fmaxf(sreg[kt][ni][0], sreg[kt][ni][1]));
            m1 = fmaxf(m1, fmaxf(sreg[kt][ni][2], sreg[kt][ni][3]));
        }
    #pragma unroll
    for (int o = 1; o <= 2; o <<= 1) {
        m0 = fmaxf(m0, __shfl_xor_sync(0xffffffffu, m0, o));
        m1 = fmaxf(m1, __shfl_xor_sync(0xffffffffu, m1, o));
    }
    if (tig == 0) {
        wmax[nw * 64 + r0] = m0;
        wmax[nw * 64 + r1] = m1;
    }
    __syncthreads();
    float rm0 = fmaxf(fmaxf(wmax[r0], wmax[64 + r0]), fmaxf(wmax[128 + r0], wmax[192 + r0]));
    float rm1 = fmaxf(fmaxf(wmax[r1], wmax[64 + r1]), fmaxf(wmax[128 + r1], wmax[192 + r1]));

    float s0 = 0.0f, s1 = 0.0f;
    #pragma unroll
    for (int kt = 0; kt < 8; kt++)
        #pragma unroll
        for (int ni = 0; ni < 2; ni++) {
            float e0 = fexp(sreg[kt][ni][0] - rm0);
            float e1 = fexp(sreg[kt][ni][1] - rm0);
            float e2 = fexp(sreg[kt][ni][2] - rm1);
            float e3 = fexp(sreg[kt][ni][3] - rm1);
            sreg[kt][ni][0] = e0; sreg[kt][ni][1] = e1;
            sreg[kt][ni][2] = e2; sreg[kt][ni][3] = e3;
            s0 += e0 + e1;
            s1 += e2 + e3;
        }
    #pragma unroll
    for (int o = 1; o <= 2; o <<= 1) {
        s0 += __shfl_xor_sync(0xffffffffu, s0, o);
        s1 += __shfl_xor_sync(0xffffffffu, s1, o);
    }
    if (tig == 0) {
        wsum[nw * 64 + r0] = s0;
        wsum[nw * 64 + r1] = s1;
    }
    CP_WAIT(0);
    __syncthreads();
    float inv0 = 1.0f / (wsum[r0] + wsum[64 + r0] + wsum[128 + r0] + wsum[192 + r0]);
    float inv1 = 1.0f / (wsum[r1] + wsum[64 + r1] + wsum[128 + r1] + wsum[192 + r1]);

    const size_t pb0 = (((size_t)b * NHH + h) * SS + q0 + r0) * SS;
    const size_t pb1 = (((size_t)b * NHH + h) * SS + q0 + r1) * SS;

    float cacc[8][4];
    #pragma unroll
    for (int nd = 0; nd < 8; nd++)
        #pragma unroll
        for (int rr = 0; rr < 4; rr++) cacc[nd][rr] = 0.0f;

    #pragma unroll
    for (int kt = 0; kt < 8; kt++) {
        uint32_t paf[4];
        #pragma unroll
        for (int ni = 0; ni < 2; ni++) {
            int col = kt * 64 + nw * 16 + ni * 8 + tig * 2;
            float p0 = sreg[kt][ni][0] * inv0;
            float p1 = sreg[kt][ni][1] * inv0;
            float p2 = sreg[kt][ni][2] * inv1;
            float p3 = sreg[kt][ni][3] * inv1;
            __stcs(reinterpret_cast<float2*>(probs + pb0 + col), make_float2(p0, p1));
            __stcs(reinterpret_cast<float2*>(probs + pb1 + col), make_float2(p2, p3));
            __half2 h01 = __floats2half2_rn(p0, p1);
            __half2 h23 = __floats2half2_rn(p2, p3);
            paf[ni * 2]     = reinterpret_cast<uint32_t&>(h01);
            paf[ni * 2 + 1] = reinterpret_cast<uint32_t&>(h23);
        }
        const uint32_t kvb = smem_base + SM_V + kt * TILE_B;
        #pragma unroll
        for (int dd = 0; dd < 4; dd++) {
            uint32_t bf[4];
            LDSM_X4T(bf[0], bf[1], bf[2], bf[3], kvb + voff + dd * 32);
            mma_fp16(cacc[dd * 2],     paf[0], paf[1], paf[2], paf[3], bf[0], bf[1]);
            mma_fp16(cacc[dd * 2 + 1], paf[0], paf[1], paf[2], paf[3], bf[2], bf[3]);
        }
    }

    #pragma unroll
    for (int nd = 0; nd < 8; nd++) {
        int d = nd * 8 + tig * 2;
        *reinterpret_cast<float2*>(ctxb + (nw * 64 + r0) * CTXST + d) =
            make_float2(cacc[nd][0], cacc[nd][1]);
        *reinterpret_cast<float2*>(ctxb + (nw * 64 + r1) * CTXST + d) =
            make_float2(cacc[nd][2], cacc[nd][3]);
    }
    __syncthreads();

    {
        int row = tid >> 3;
        int d0  = (tid & 7) * 8;
        #pragma unroll
        for (int half = 0; half < 2; half++) {
            int d = d0 + half * 4;
            float4 v0 = *reinterpret_cast<float4*>(ctxb + (0 * 64 + row) * CTXST + d);
            float4 v1 = *reinterpret_cast<float4*>(ctxb + (1 * 64 + row) * CTXST + d);
            float4 v2 = *reinterpret_cast<float4*>(ctxb + (2 * 64 + row) * CTXST + d);
            float4 v3 = *reinterpret_cast<float4*>(ctxb + (3 * 64 + row) * CTXST + d);
            float4 o;
            o.x = v0.x + v1.x + v2.x + v3.x;
            o.y = v0.y + v1.y + v2.y + v3.y;
            o.z = v0.z + v1.z + v2.z + v3.z;
            o.w = v0.w + v1.w + v2.w + v3.w;
            *reinterpret_cast<float4*>(
                ctx + ((size_t)(b * SS + q0 + row)) * HH + h * HDD + d) = o;
        }
    }
}

// ---------------------------------------------------------------------------
// kernel_launch
// ---------------------------------------------------------------------------
extern "C" void kernel_launch(void* const* d_in, const int* in_sizes, int n_in,
                              void* d_out, int out_size)
{
    const float* hidden = (const float*)d_in[0];
    const float* mask   = (const float*)d_in[1];
    const float* Wq = (const float*)d_in[2];
    const float* bq = (const float*)d_in[3];
    const float* Wk = (const float*)d_in[4];
    const float* bk = (const float*)d_in[5];
    const float* Wv = (const float*)d_in[6];
    const float* bv = (const float*)d_in[7];

    float* out   = (float*)d_out;
    float* ctx   = out;
    float* probs = out + (size_t)BB * SS * HH;

    // 0) fp32 -> fp16
    int nblk = (int)((NTOT4 / 2 + 255) / 256);
    split_kernel<<<nblk, 256>>>(hidden, Wq, Wk, Wv);

    // 1) QKV projections (fp16 mma.sync, 128x256 block, 512 threads, 64x32 warp tiles)
    cudaFuncSetAttribute(qkv_gemm_mma, cudaFuncAttributeMaxDynamicSharedMemorySize, GEMM_SMEM_TOTAL);
    dim3 g1(HH / 256, MROWS / 128, 3);
    qkv_gemm_mma<<<g1, 512, GEMM_SMEM_TOTAL>>>(bq, bk, bv);

    // 2) fused attention (register-resident, full K/V preload)
    cudaFuncSetAttribute(attn_kernel, cudaFuncAttributeMaxDynamicSharedMemorySize, ATTN_SMEM_TOTAL);
    dim3 g2(SS / 64, NHH, BB);
    attn_kernel<<<g2, 512, ATTN_SMEM_TOTAL>>>(mask, ctx, probs);
}

// round 14
// speedup vs baseline: 1.0297x; 1.0112x over previous
#include <cuda_runtime.h>
#include <cuda_fp16.h>
#include <cstdint>
#include <math.h>

// Problem constants
static constexpr int BB = 16;     // batch
static constexpr int SS = 512;    // seq len
static constexpr int HH = 768;    // hidden
static constexpr int NHH = 12;    // heads
static constexpr int HDD = 64;    // head dim
static constexpr int MROWS = BB * SS;  // 8192

// Scratch (static device allocations allowed)
__device__ __half g_qkvh[3][(size_t)MROWS * HH];   // fp16 Q,K,V
__device__ __half g_xh[(size_t)MROWS * HH];        // fp16 hidden
__device__ __half g_wh[3][(size_t)HH * HH];        // fp16 weights

// ---------------------------------------------------------------------------
// helpers
// ---------------------------------------------------------------------------
__device__ __forceinline__ uint32_t smem_to_u32(const void* p) {
    uint32_t a;
    asm("{ .reg .u64 t; cvta.to.shared.u64 t, %1; cvt.u32.u64 %0, t; }" : "=r"(a) : "l"(p));
    return a;
}
#define CP_ASYNC16(dst_u32, src_ptr) \
    asm volatile("cp.async.cg.shared.global [%0], [%1], 16;" :: "r"(dst_u32), "l"(src_ptr) : "memory")
#define CP_COMMIT() asm volatile("cp.async.commit_group;" ::: "memory")
#define CP_WAIT(n)  asm volatile("cp.async.wait_group %0;" :: "n"(n) : "memory")

#define LDSM_X4(r0, r1, r2, r3, a) \
    asm volatile("ldmatrix.sync.aligned.m8n8.x4.shared.b16 {%0,%1,%2,%3}, [%4];" \
                 : "=r"(r0), "=r"(r1), "=r"(r2), "=r"(r3) : "r"(a))
#define LDSM_X4T(r0, r1, r2, r3, a) \
    asm volatile("ldmatrix.sync.aligned.m8n8.x4.trans.shared.b16 {%0,%1,%2,%3}, [%4];" \
                 : "=r"(r0), "=r"(r1), "=r"(r2), "=r"(r3) : "r"(a))

__device__ __forceinline__ void mma_fp16(float d[4],
                                         uint32_t a0, uint32_t a1, uint32_t a2, uint32_t a3,
                                         uint32_t b0, uint32_t b1) {
    asm volatile(
        "mma.sync.aligned.m16n8k16.row.col.f32.f16.f16.f32 "
        "{%0,%1,%2,%3}, {%4,%5,%6,%7}, {%8,%9}, {%0,%1,%2,%3};"
        : "+f"(d[0]), "+f"(d[1]), "+f"(d[2]), "+f"(d[3])
        : "r"(a0), "r"(a1), "r"(a2), "r"(a3), "r"(b0), "r"(b1));
}

// FMA-only exp (no MUFU): e^x = 2^(x*log2e)
__device__ __forceinline__ float fexp(float x) {
    float y = x * 1.4426950408889634f;
    y = fmaxf(y, -120.0f);
    float r = rintf(y);
    float f = y - r;
    float p = 1.5403530393381609e-4f;
    p = fmaf(p, f, 1.3333558146428443e-3f);
    p = fmaf(p, f, 9.6181291076284770e-3f);
    p = fmaf(p, f, 5.5504108664821580e-2f);
    p = fmaf(p, f, 2.4022650695910070e-1f);
    p = fmaf(p, f, 6.9314718055994531e-1f);
    p = fmaf(p, f, 1.0f);
    int i = (int)r;
    float s = __int_as_float((i + 127) << 23);
    return p * s;
}

// ---------------------------------------------------------------------------
// Kernel 0: fp32 -> fp16 conversion, 4 independent float4 per thread (MLP=4).
// Loads batched before converts/stores to maximize outstanding loads.
// ---------------------------------------------------------------------------
static constexpr size_t NX4 = (size_t)MROWS * HH / 4;
static constexpr size_t NW4 = (size_t)HH * HH / 4;
static constexpr size_t NTOT4 = NX4 + 3 * NW4;

__device__ __forceinline__ const float* split_src(
    const float* __restrict__ X,
    const float* __restrict__ Wq, const float* __restrict__ Wk, const float* __restrict__ Wv,
    size_t i, __half** dst_out, size_t* off_out)
{
    if (i < NX4) { *dst_out = g_xh; *off_out = i; return X; }
    size_t j = i - NX4;
    int w = (int)(j / NW4);
    *off_out = j - (size_t)w * NW4;
    *dst_out = g_wh[w];
    return (w == 0) ? Wq : (w == 1) ? Wk : Wv;
}

__global__ __launch_bounds__(256) void split_kernel(
    const float* __restrict__ X,
    const float* __restrict__ Wq, const float* __restrict__ Wk, const float* __restrict__ Wv)
{
    const size_t stride = (size_t)gridDim.x * blockDim.x;
    const size_t base = (size_t)blockIdx.x * blockDim.x + threadIdx.x;

    float4 v[4];
    __half* dst[4];
    size_t off[4];
    bool ok[4];

    #pragma unroll
    for (int e = 0; e < 4; e++) {
        size_t i = base + e * stride;
        ok[e] = (i < NTOT4);
        if (ok[e]) {
            const float* src = split_src(X, Wq, Wk, Wv, i, &dst[e], &off[e]);
            v[e] = reinterpret_cast<const float4*>(src)[off[e]];
        }
    }
    #pragma unroll
    for (int e = 0; e < 4; e++) {
        if (ok[e]) {
            __half2 h0 = __floats2half2_rn(v[e].x, v[e].y);
            __half2 h1 = __floats2half2_rn(v[e].z, v[e].w);
            uint2 st;
            st.x = reinterpret_cast<uint32_t&>(h0);
            st.y = reinterpret_cast<uint32_t&>(h1);
            *reinterpret_cast<uint2*>(dst[e] + 4 * off[e]) = st;
        }
    }
}

// ---------------------------------------------------------------------------
// Kernel 1: QKV projection — EXACT round-11 config (proven fastest):
// block tile 128x128, 256 threads, 8 warps 2(m)x4(n), warp tile 64x32,
// BK=64, 3-stage ring, prefetch distance 1, 1 barrier/iter, 2 CTAs/SM.
// ---------------------------------------------------------------------------
static constexpr int BK = 64;
static constexpr int KSTRIDE = 72;
static constexpr int TILE_BYTES_G = 128 * KSTRIDE * 2;   // 18432
static constexpr int STAGE_BYTES = 2 * TILE_BYTES_G;     // 36864
static constexpr int GEMM_SMEM_TOTAL = 3 * STAGE_BYTES;  // 110592
static constexpr int NKT = HH / BK;                      // 12

__device__ __forceinline__ void load_stage_async(
    char* smem, int s,
    const __half* __restrict__ A, const __half* __restrict__ B,
    int k0, int tid)
{
    char* base = smem + s * STAGE_BYTES;
    #pragma unroll
    for (int e = 0; e < 8; e++) {
        const int tile = e >> 2;
        int idx = ((e & 3) << 8) + tid;
        int r = idx >> 3;
        int q = idx & 7;
        const __half* src = (tile == 0 ? A : B) + (size_t)r * HH + k0 + q * 8;
        uint32_t dst = smem_to_u32(base + tile * TILE_BYTES_G + (r * KSTRIDE + q * 8) * 2);
        CP_ASYNC16(dst, src);
    }
}

__global__ __launch_bounds__(256, 2) void qkv_gemm_mma(
    const float* __restrict__ bq, const float* __restrict__ bk, const float* __restrict__ bv)
{
    extern __shared__ char smem[];
    const uint32_t smem_base = smem_to_u32(smem);
    const int tid = threadIdx.x;
    const int wid = tid >> 5;
    const int lane = tid & 31;
    const int g = lane >> 2;
    const int tig = lane & 3;

    const int which = blockIdx.z;
    const int n0 = blockIdx.x * 128;
    const int m0 = blockIdx.y * 128;
    const float* bias = (which == 0) ? bq : (which == 1) ? bk : bv;
    __half* out = g_qkvh[which];

    const __half* A = g_xh + (size_t)m0 * HH;
    const __half* B = g_wh[which] + (size_t)n0 * HH;

    const int m_w = (wid & 1) * 64;
    const int n_w = (wid >> 1) * 32;

    const uint32_t aoff = ((m_w + (lane & 15)) * KSTRIDE + (lane >> 4) * 8) * 2;
    const uint32_t boff = ((n_w + ((lane >> 4) & 1) * 8 + (lane & 7)) * KSTRIDE
                           + ((lane >> 3) & 1) * 8) * 2;

    float acc[4][4][4];
    #pragma unroll
    for (int i = 0; i < 4; i++)
        #pragma unroll
        for (int j = 0; j < 4; j++)
            #pragma unroll
            for (int r = 0; r < 4; r++) acc[i][j][r] = 0.0f;

    load_stage_async(smem, 0, A, B, 0, tid);
    CP_COMMIT();

    for (int kt = 0; kt < NKT; kt++) {
        const int s = kt % 3;
        if (kt + 1 < NKT) {
            load_stage_async(smem, (kt + 1) % 3, A, B, (kt + 1) * BK, tid);
            CP_COMMIT();
            CP_WAIT(1);
        } else {
            CP_WAIT(0);
        }
        __syncthreads();
        // single barrier per iter: 3-stage ring, prefetch distance 1 —
        // writer at iter kt+1 targets stage (kt+2)%3; slowest reader (past
        // barrier kt) reads stage kt%3; distances 1,2 mod 3 — no aliasing.

        const uint32_t sA = smem_base + s * STAGE_BYTES;
        const uint32_t sB = sA + TILE_BYTES_G;

        #pragma unroll
        for (int kc = 0; kc < 4; kc++) {
            uint32_t a[4][4];
            #pragma unroll
            for (int mi = 0; mi < 4; mi++)
                LDSM_X4(a[mi][0], a[mi][1], a[mi][2], a[mi][3],
                        sA + aoff + mi * 16 * KSTRIDE * 2 + kc * 32);
            uint32_t b[2][4];
            #pragma unroll
            for (int n2 = 0; n2 < 2; n2++)
                LDSM_X4(b[n2][0], b[n2][1], b[n2][2], b[n2][3],
                        sB + boff + n2 * 16 * KSTRIDE * 2 + kc * 32);
            #pragma unroll
            for (int mi = 0; mi < 4; mi++)
                #pragma unroll
                for (int ni = 0; ni < 4; ni++)
                    mma_fp16(acc[mi][ni], a[mi][0], a[mi][1], a[mi][2], a[mi][3],
                             b[ni >> 1][(ni & 1) * 2], b[ni >> 1][(ni & 1) * 2 + 1]);
        }
    }

    #pragma unroll
    for (int mi = 0; mi < 4; mi++) {
        int row = m0 + m_w + mi * 16 + g;
        #pragma unroll
        for (int ni = 0; ni < 4; ni++) {
            int n = n0 + n_w + ni * 8 + tig * 2;
            float b0f = bias[n], b1f = bias[n + 1];
            __half2 v0 = __floats2half2_rn(acc[mi][ni][0] + b0f, acc[mi][ni][1] + b1f);
            __half2 v1 = __floats2half2_rn(acc[mi][ni][2] + b0f, acc[mi][ni][3] + b1f);
            *reinterpret_cast<__half2*>(out + (size_t)row * HH + n) = v0;
            *reinterpret_cast<__half2*>(out + (size_t)(row + 8) * HH + n) = v1;
        }
    }
}

// ---------------------------------------------------------------------------
// Kernel 2: register-resident flash-style attention (round-11 proven version).
// ---------------------------------------------------------------------------
static constexpr int TST = 72;
static constexpr int TILE_B = 64 * TST * 2;

static constexpr int SM_Q    = 0;
static constexpr int SM_K    = SM_Q + TILE_B;
static constexpr int SM_V    = SM_K + 8 * TILE_B;
static constexpr int SM_MSK  = SM_V + 8 * TILE_B;
static constexpr int SM_WMAX = SM_MSK + SS * 4;
static constexpr int SM_WSUM = SM_WMAX + 4 * 64 * 4;
static constexpr int ATTN_SMEM_TOTAL = SM_WSUM + 4 * 64 * 4;
static constexpr int CTXST = 68;

__global__ __launch_bounds__(512, 1) void attn_kernel(
    const float* __restrict__ mask,
    float* __restrict__ ctx,
    float* __restrict__ probs)
{
    extern __shared__ char smem[];
    const uint32_t smem_base = smem_to_u32(smem);
    float* msk   = (float*)(smem + SM_MSK);
    float* wmax  = (float*)(smem + SM_WMAX);
    float* wsum  = (float*)(smem + SM_WSUM);
    float* ctxb  = (float*)(smem + SM_K);     // aliases K region

    const int qt = blockIdx.x;
    const int h  = blockIdx.y;
    const int b  = blockIdx.z;
    const int tid  = threadIdx.x;
    const int lane = tid & 31;
    const int g    = lane >> 2;
    const int tig  = lane & 3;
    const int mw   = ((tid >> 5) & 3);
    const int nw   = (tid >> 7);
    const int q0 = qt * 64;
    const float scale = 0.125f;

    const __half* Q = g_qkvh[0];
    const __half* K = g_qkvh[1];
    const __half* V = g_qkvh[2];

    msk[tid] = (1.0f - mask[(size_t)b * SS + tid]) * -10000.0f;

    const int r = tid >> 3, q = tid & 7;

    {
        uint4 v = *reinterpret_cast<const uint4*>(
            Q + ((size_t)(b * SS + q0 + r)) * HH + h * HDD + q * 8);
        *reinterpret_cast<uint4*>((__half*)(smem + SM_Q) + r * TST + q * 8) = v;
    }
    // K commits: tile0, tile1, {2,3}, {4,5}, {6,7}; V -> 1 group
    #pragma unroll
    for (int kt = 0; kt < 8; kt++) {
        CP_ASYNC16(smem_base + SM_K + kt * TILE_B + r * TST * 2 + q * 16,
                   K + ((size_t)(b * SS + kt * 64 + r)) * HH + h * HDD + q * 8);
        if (kt == 0 || kt == 1 || kt == 3 || kt == 5 || kt == 7) CP_COMMIT();
    }
    #pragma unroll
    for (int kt = 0; kt < 8; kt++) {
        CP_ASYNC16(smem_base + SM_V + kt * TILE_B + r * TST * 2 + q * 16,
                   V + ((size_t)(b * SS + kt * 64 + r)) * HH + h * HDD + q * 8);
    }
    CP_COMMIT();

    const uint32_t koff = (nw * 16 + ((lane >> 4) & 1) * 8 + (lane & 7)) * TST * 2
                          + ((lane >> 3) & 1) * 16;
    const uint32_t voff = (nw * 16 + (lane & 7) + ((lane >> 3) & 1) * 8) * TST * 2
                          + ((lane >> 4) & 1) * 16;

    CP_WAIT(5);
    __syncthreads();

    uint32_t qf[4][4];
    {
        const uint32_t qbase = smem_base + SM_Q
            + ((mw * 16 + (lane & 15)) * TST) * 2 + (lane >> 4) * 16;
        #pragma unroll
        for (int kc = 0; kc < 4; kc++)
            LDSM_X4(qf[kc][0], qf[kc][1], qf[kc][2], qf[kc][3], qbase + kc * 32);
    }

    float sreg[8][2][4];
    #pragma unroll
    for (int kt = 0; kt < 8; kt++) {
        if (kt == 1)      { CP_WAIT(4); __syncthreads(); }
        else if (kt == 2) { CP_WAIT(3); __syncthreads(); }
        else if (kt == 4) { CP_WAIT(2); __syncthreads(); }
        else if (kt == 6) { CP_WAIT(1); __syncthreads(); }

        const uint32_t kvb = smem_base + SM_K + kt * TILE_B;
        float acc[2][4];
        #pragma unroll
        for (int ni = 0; ni < 2; ni++)
            #pragma unroll
            for (int rr = 0; rr < 4; rr++) acc[ni][rr] = 0.0f;

        #pragma unroll
        for (int kc = 0; kc < 4; kc++) {
            uint32_t bf[4];
            LDSM_X4(bf[0], bf[1], bf[2], bf[3], kvb + koff + kc * 32);
            mma_fp16(acc[0], qf[kc][0], qf[kc][1], qf[kc][2], qf[kc][3], bf[0], bf[1]);
            mma_fp16(acc[1], qf[kc][0], qf[kc][1], qf[kc][2], qf[kc][3], bf[2], bf[3]);
        }
        #pragma unroll
        for (int ni = 0; ni < 2; ni++) {
            int col = kt * 64 + nw * 16 + ni * 8 + tig * 2;
            sreg[kt][ni][0] = acc[ni][0] * scale + msk[col];
            sreg[kt][ni][1] = acc[ni][1] * scale + msk[col + 1];
            sreg[kt][ni][2] = acc[ni][2] * scale + msk[col];
            sreg[kt][ni][3] = acc[ni][3] * scale + msk[col + 1];
        }
    }

    const int r0 = mw * 16 + g;
    const int r1 = r0 + 8;

    float m0 = -1e30f, m1 = -1e30f;
    #pragma unroll
    for (int kt = 0; kt < 8; kt++)
        #pragma unroll
        for (int ni = 0; ni < 2; ni++) {
            m0 = fmaxf(m0, fmaxf(sreg[kt][ni][0], sreg[kt][ni][1]));
            m1 = fmaxf(m1, fmaxf(sreg[kt][ni][2], sreg[kt][ni][3]));
        }
    #pragma unroll
    for (int o = 1; o <= 2; o <<= 1) {
        m0 = fmaxf(m0, __shfl_xor_sync(0xffffffffu, m0, o));
        m1 = fmaxf(m1, __shfl_xor_sync(0xffffffffu, m1, o));
    }
    if (tig == 0) {
        wmax[nw * 64 + r0] = m0;
        wmax[nw * 64 + r1] = m1;
    }
    __syncthreads();
    float rm0 = fmaxf(fmaxf(wmax[r0], wmax[64 + r0]), fmaxf(wmax[128 + r0], wmax[192 + r0]));
    float rm1 = fmaxf(fmaxf(wmax[r1], wmax[64 + r1]), fmaxf(wmax[128 + r1], wmax[192 + r1]));

    float s0 = 0.0f, s1 = 0.0f;
    #pragma unroll
    for (int kt = 0; kt < 8; kt++)
        #pragma unroll
        for (int ni = 0; ni < 2; ni++) {
            float e0 = fexp(sreg[kt][ni][0] - rm0);
            float e1 = fexp(sreg[kt][ni][1] - rm0);
            float e2 = fexp(sreg[kt][ni][2] - rm1);
            float e3 = fexp(sreg[kt][ni][3] - rm1);
            sreg[kt][ni][0] = e0; sreg[kt][ni][1] = e1;
            sreg[kt][ni][2] = e2; sreg[kt][ni][3] = e3;
            s0 += e0 + e1;
            s1 += e2 + e3;
        }
    #pragma unroll
    for (int o = 1; o <= 2; o <<= 1) {
        s0 += __shfl_xor_sync(0xffffffffu, s0, o);
        s1 += __shfl_xor_sync(0xffffffffu, s1, o);
    }
    if (tig == 0) {
        wsum[nw * 64 + r0] = s0;
        wsum[nw * 64 + r1] = s1;
    }
    CP_WAIT(0);
    __syncthreads();
    float inv0 = 1.0f / (wsum[r0] + wsum[64 + r0] + wsum[128 + r0] + wsum[192 + r0]);
    float inv1 = 1.0f / (wsum[r1] + wsum[64 + r1] + wsum[128 + r1] + wsum[192 + r1]);

    const size_t pb0 = (((size_t)b * NHH + h) * SS + q0 + r0) * SS;
    const size_t pb1 = (((size_t)b * NHH + h) * SS + q0 + r1) * SS;

    float cacc[8][4];
    #pragma unroll
    for (int nd = 0; nd < 8; nd++)
        #pragma unroll
        for (int rr = 0; rr < 4; rr++) cacc[nd][rr] = 0.0f;

    #pragma unroll
    for (int kt = 0; kt < 8; kt++) {
        uint32_t paf[4];
        #pragma unroll
        for (int ni = 0; ni < 2; ni++) {
            int col = kt * 64 + nw * 16 + ni * 8 + tig * 2;
            float p0 = sreg[kt][ni][0] * inv0;
            float p1 = sreg[kt][ni][1] * inv0;
            float p2 = sreg[kt][ni][2] * inv1;
            float p3 = sreg[kt][ni][3] * inv1;
            __stcs(reinterpret_cast<float2*>(probs + pb0 + col), make_float2(p0, p1));
            __stcs(reinterpret_cast<float2*>(probs + pb1 + col), make_float2(p2, p3));
            __half2 h01 = __floats2half2_rn(p0, p1);
            __half2 h23 = __floats2half2_rn(p2, p3);
            paf[ni * 2]     = reinterpret_cast<uint32_t&>(h01);
            paf[ni * 2 + 1] = reinterpret_cast<uint32_t&>(h23);
        }
        const uint32_t kvb = smem_base + SM_V + kt * TILE_B;
        #pragma unroll
        for (int dd = 0; dd < 4; dd++) {
            uint32_t bf[4];
            LDSM_X4T(bf[0], bf[1], bf[2], bf[3], kvb + voff + dd * 32);
            mma_fp16(cacc[dd * 2],     paf[0], paf[1], paf[2], paf[3], bf[0], bf[1]);
            mma_fp16(cacc[dd * 2 + 1], paf[0], paf[1], paf[2], paf[3], bf[2], bf[3]);
        }
    }

    #pragma unroll
    for (int nd = 0; nd < 8; nd++) {
        int d = nd * 8 + tig * 2;
        *reinterpret_cast<float2*>(ctxb + (nw * 64 + r0) * CTXST + d) =
            make_float2(cacc[nd][0], cacc[nd][1]);
        *reinterpret_cast<float2*>(ctxb + (nw * 64 + r1) * CTXST + d) =
            make_float2(cacc[nd][2], cacc[nd][3]);
    }
    __syncthreads();

    {
        int row = tid >> 3;
        int d0  = (tid & 7) * 8;
        #pragma unroll
        for (int half = 0; half < 2; half++) {
            int d = d0 + half * 4;
            float4 v0 = *reinterpret_cast<float4*>(ctxb + (0 * 64 + row) * CTXST + d);
            float4 v1 = *reinterpret_cast<float4*>(ctxb + (1 * 64 + row) * CTXST + d);
            float4 v2 = *reinterpret_cast<float4*>(ctxb + (2 * 64 + row) * CTXST + d);
            float4 v3 = *reinterpret_cast<float4*>(ctxb + (3 * 64 + row) * CTXST + d);
            float4 o;
            o.x = v0.x + v1.x + v2.x + v3.x;
            o.y = v0.y + v1.y + v2.y + v3.y;
            o.z = v0.z + v1.z + v2.z + v3.z;
            o.w = v0.w + v1.w + v2.w + v3.w;
            *reinterpret_cast<float4*>(
                ctx + ((size_t)(b * SS + q0 + row)) * HH + h * HDD + d) = o;
        }
    }
}

// ---------------------------------------------------------------------------
// kernel_launch
// ---------------------------------------------------------------------------
extern "C" void kernel_launch(void* const* d_in, const int* in_sizes, int n_in,
                              void* d_out, int out_size)
{
    const float* hidden = (const float*)d_in[0];
    const float* mask   = (const float*)d_in[1];
    const float* Wq = (const float*)d_in[2];
    const float* bq = (const float*)d_in[3];
    const float* Wk = (const float*)d_in[4];
    const float* bk = (const float*)d_in[5];
    const float* Wv = (const float*)d_in[6];
    const float* bv = (const float*)d_in[7];

    float* out   = (float*)d_out;
    float* ctx   = out;
    float* probs = out + (size_t)BB * SS * HH;

    // 0) fp32 -> fp16 (4 independent float4 per thread)
    int nblk = (int)((NTOT4 / 4 + 255) / 256);
    split_kernel<<<nblk, 256>>>(hidden, Wq, Wk, Wv);

    // 1) QKV projections (fp16 mma.sync, round-11 proven config)
    cudaFuncSetAttribute(qkv_gemm_mma, cudaFuncAttributeMaxDynamicSharedMemorySize, GEMM_SMEM_TOTAL);
    dim3 g1(HH / 128, MROWS / 128, 3);
    qkv_gemm_mma<<<g1, 256, GEMM_SMEM_TOTAL>>>(bq, bk, bv);

    // 2) fused attention (register-resident, full K/V preload)
    cudaFuncSetAttribute(attn_kernel, cudaFuncAttributeMaxDynamicSharedMemorySize, ATTN_SMEM_TOTAL);
    dim3 g2(SS / 64, NHH, BB);
    attn_kernel<<<g2, 512, ATTN_SMEM_TOTAL>>>(mask, ctx, probs);
}

// round 15
// speedup vs baseline: 1.0460x; 1.0159x over previous
#include <cuda_runtime.h>
#include <cuda_fp16.h>
#include <cstdint>
#include <math.h>

// Problem constants
static constexpr int BB = 16;     // batch
static constexpr int SS = 512;    // seq len
static constexpr int HH = 768;    // hidden
static constexpr int NHH = 12;    // heads
static constexpr int HDD = 64;    // head dim
static constexpr int MROWS = BB * SS;  // 8192

// Q pre-scale: 1/sqrt(64) * log2(e)  (scores come out in log2 domain)
#define QSCALE 0.1803368801111394f
#define MSCALE (-14426.950408889634f)   // -10000 * log2(e)

// Scratch (static device allocations allowed)
__device__ __half g_qkvh[3][(size_t)MROWS * HH];   // fp16 Q,K,V
__device__ __half g_xh[(size_t)MROWS * HH];        // fp16 hidden
__device__ __half g_wh[3][(size_t)HH * HH];        // fp16 weights

// ---------------------------------------------------------------------------
// helpers
// ---------------------------------------------------------------------------
__device__ __forceinline__ uint32_t smem_to_u32(const void* p) {
    uint32_t a;
    asm("{ .reg .u64 t; cvta.to.shared.u64 t, %1; cvt.u32.u64 %0, t; }" : "=r"(a) : "l"(p));
    return a;
}
#define CP_ASYNC16(dst_u32, src_ptr) \
    asm volatile("cp.async.cg.shared.global [%0], [%1], 16;" :: "r"(dst_u32), "l"(src_ptr) : "memory")
#define CP_COMMIT() asm volatile("cp.async.commit_group;" ::: "memory")
#define CP_WAIT(n)  asm volatile("cp.async.wait_group %0;" :: "n"(n) : "memory")

#define LDSM_X4(r0, r1, r2, r3, a) \
    asm volatile("ldmatrix.sync.aligned.m8n8.x4.shared.b16 {%0,%1,%2,%3}, [%4];" \
                 : "=r"(r0), "=r"(r1), "=r"(r2), "=r"(r3) : "r"(a))
#define LDSM_X4T(r0, r1, r2, r3, a) \
    asm volatile("ldmatrix.sync.aligned.m8n8.x4.trans.shared.b16 {%0,%1,%2,%3}, [%4];" \
                 : "=r"(r0), "=r"(r1), "=r"(r2), "=r"(r3) : "r"(a))

__device__ __forceinline__ void mma_fp16(float d[4],
                                         uint32_t a0, uint32_t a1, uint32_t a2, uint32_t a3,
                                         uint32_t b0, uint32_t b1) {
    asm volatile(
        "mma.sync.aligned.m16n8k16.row.col.f32.f16.f16.f32 "
        "{%0,%1,%2,%3}, {%4,%5,%6,%7}, {%8,%9}, {%0,%1,%2,%3};"
        : "+f"(d[0]), "+f"(d[1]), "+f"(d[2]), "+f"(d[3])
        : "r"(a0), "r"(a1), "r"(a2), "r"(a3), "r"(b0), "r"(b1));
}

// FMA-only 2^y (input already in log2 domain, y <= 0).
// Round-to-nearest via magic-number add; degree-6 2^f polynomial.
__device__ __forceinline__ float fexp2(float y) {
    y = fmaxf(y, -120.0f);
    float t = y + 12582912.0f;            // 1.5 * 2^23 : RN to integer
    float f = y - (t - 12582912.0f);      // f in [-0.5, 0.5]
    int k = __float_as_int(t) + (127 - 0x4B400000);
    float s = __int_as_float(k << 23);    // 2^n
    float p = 1.5403530393381609e-4f;
    p = fmaf(p, f, 1.3333558146428443e-3f);
    p = fmaf(p, f, 9.6181291076284770e-3f);
    p = fmaf(p, f, 5.5504108664821580e-2f);
    p = fmaf(p, f, 2.4022650695910070e-1f);
    p = fmaf(p, f, 6.9314718055994531e-1f);
    p = fmaf(p, f, 1.0f);
    return p * s;
}

// ---------------------------------------------------------------------------
// Kernel 0: fp32 -> fp16 conversion, 4 independent float4 per thread.
// ---------------------------------------------------------------------------
static constexpr size_t NX4 = (size_t)MROWS * HH / 4;
static constexpr size_t NW4 = (size_t)HH * HH / 4;
static constexpr size_t NTOT4 = NX4 + 3 * NW4;

__device__ __forceinline__ const float* split_src(
    const float* __restrict__ X,
    const float* __restrict__ Wq, const float* __restrict__ Wk, const float* __restrict__ Wv,
    size_t i, __half** dst_out, size_t* off_out)
{
    if (i < NX4) { *dst_out = g_xh; *off_out = i; return X; }
    size_t j = i - NX4;
    int w = (int)(j / NW4);
    *off_out = j - (size_t)w * NW4;
    *dst_out = g_wh[w];
    return (w == 0) ? Wq : (w == 1) ? Wk : Wv;
}

__global__ __launch_bounds__(256) void split_kernel(
    const float* __restrict__ X,
    const float* __restrict__ Wq, const float* __restrict__ Wk, const float* __restrict__ Wv)
{
    const size_t stride = (size_t)gridDim.x * blockDim.x;
    const size_t base = (size_t)blockIdx.x * blockDim.x + threadIdx.x;

    float4 v[4];
    __half* dst[4];
    size_t off[4];
    bool ok[4];

    #pragma unroll
    for (int e = 0; e < 4; e++) {
        size_t i = base + e * stride;
        ok[e] = (i < NTOT4);
        if (ok[e]) {
            const float* src = split_src(X, Wq, Wk, Wv, i, &dst[e], &off[e]);
            v[e] = reinterpret_cast<const float4*>(src)[off[e]];
        }
    }
    #pragma unroll
    for (int e = 0; e < 4; e++) {
        if (ok[e]) {
            __half2 h0 = __floats2half2_rn(v[e].x, v[e].y);
            __half2 h1 = __floats2half2_rn(v[e].z, v[e].w);
            uint2 st;
            st.x = reinterpret_cast<uint32_t&>(h0);
            st.y = reinterpret_cast<uint32_t&>(h1);
            *reinterpret_cast<uint2*>(dst[e] + 4 * off[e]) = st;
        }
    }
}

// ---------------------------------------------------------------------------
// Kernel 1: QKV projection — round-11 proven config; Q epilogue pre-scaled.
// ---------------------------------------------------------------------------
static constexpr int BK = 64;
static constexpr int KSTRIDE = 72;
static constexpr int TILE_BYTES_G = 128 * KSTRIDE * 2;   // 18432
static constexpr int STAGE_BYTES = 2 * TILE_BYTES_G;     // 36864
static constexpr int GEMM_SMEM_TOTAL = 3 * STAGE_BYTES;  // 110592
static constexpr int NKT = HH / BK;                      // 12

__device__ __forceinline__ void load_stage_async(
    char* smem, int s,
    const __half* __restrict__ A, const __half* __restrict__ B,
    int k0, int tid)
{
    char* base = smem + s * STAGE_BYTES;
    #pragma unroll
    for (int e = 0; e < 8; e++) {
        const int tile = e >> 2;
        int idx = ((e & 3) << 8) + tid;
        int r = idx >> 3;
        int q = idx & 7;
        const __half* src = (tile == 0 ? A : B) + (size_t)r * HH + k0 + q * 8;
        uint32_t dst = smem_to_u32(base + tile * TILE_BYTES_G + (r * KSTRIDE + q * 8) * 2);
        CP_ASYNC16(dst, src);
    }
}

__global__ __launch_bounds__(256, 2) void qkv_gemm_mma(
    const float* __restrict__ bq, const float* __restrict__ bk, const float* __restrict__ bv)
{
    extern __shared__ char smem[];
    const uint32_t smem_base = smem_to_u32(smem);
    const int tid = threadIdx.x;
    const int wid = tid >> 5;
    const int lane = tid & 31;
    const int g = lane >> 2;
    const int tig = lane & 3;

    const int which = blockIdx.z;
    const int n0 = blockIdx.x * 128;
    const int m0 = blockIdx.y * 128;
    const float* bias = (which == 0) ? bq : (which == 1) ? bk : bv;
    __half* out = g_qkvh[which];
    const float osc = (which == 0) ? QSCALE : 1.0f;   // pre-scale Q

    const __half* A = g_xh + (size_t)m0 * HH;
    const __half* B = g_wh[which] + (size_t)n0 * HH;

    const int m_w = (wid & 1) * 64;
    const int n_w = (wid >> 1) * 32;

    const uint32_t aoff = ((m_w + (lane & 15)) * KSTRIDE + (lane >> 4) * 8) * 2;
    const uint32_t boff = ((n_w + ((lane >> 4) & 1) * 8 + (lane & 7)) * KSTRIDE
                           + ((lane >> 3) & 1) * 8) * 2;

    float acc[4][4][4];
    #pragma unroll
    for (int i = 0; i < 4; i++)
        #pragma unroll
        for (int j = 0; j < 4; j++)
            #pragma unroll
            for (int r = 0; r < 4; r++) acc[i][j][r] = 0.0f;

    load_stage_async(smem, 0, A, B, 0, tid);
    CP_COMMIT();

    for (int kt = 0; kt < NKT; kt++) {
        const int s = kt % 3;
        if (kt + 1 < NKT) {
            load_stage_async(smem, (kt + 1) % 3, A, B, (kt + 1) * BK, tid);
            CP_COMMIT();
            CP_WAIT(1);
        } else {
            CP_WAIT(0);
        }
        __syncthreads();
        // single barrier per iter (3-stage ring, distance-1 prefetch; no aliasing)

        const uint32_t sA = smem_base + s * STAGE_BYTES;
        const uint32_t sB = sA + TILE_BYTES_G;

        #pragma unroll
        for (int kc = 0; kc < 4; kc++) {
            uint32_t a[4][4];
            #pragma unroll
            for (int mi = 0; mi < 4; mi++)
                LDSM_X4(a[mi][0], a[mi][1], a[mi][2], a[mi][3],
                        sA + aoff + mi * 16 * KSTRIDE * 2 + kc * 32);
            uint32_t b[2][4];
            #pragma unroll
            for (int n2 = 0; n2 < 2; n2++)
                LDSM_X4(b[n2][0], b[n2][1], b[n2][2], b[n2][3],
                        sB + boff + n2 * 16 * KSTRIDE * 2 + kc * 32);
            #pragma unroll
            for (int mi = 0; mi < 4; mi++)
                #pragma unroll
                for (int ni = 0; ni < 4; ni++)
                    mma_fp16(acc[mi][ni], a[mi][0], a[mi][1], a[mi][2], a[mi][3],
                             b[ni >> 1][(ni & 1) * 2], b[ni >> 1][(ni & 1) * 2 + 1]);
        }
    }

    #pragma unroll
    for (int mi = 0; mi < 4; mi++) {
        int row = m0 + m_w + mi * 16 + g;
        #pragma unroll
        for (int ni = 0; ni < 4; ni++) {
            int n = n0 + n_w + ni * 8 + tig * 2;
            float b0f = bias[n] * osc, b1f = bias[n + 1] * osc;
            __half2 v0 = __floats2half2_rn(fmaf(acc[mi][ni][0], osc, b0f),
                                           fmaf(acc[mi][ni][1], osc, b1f));
            __half2 v1 = __floats2half2_rn(fmaf(acc[mi][ni][2], osc, b0f),
                                           fmaf(acc[mi][ni][3], osc, b1f));
            *reinterpret_cast<__half2*>(out + (size_t)row * HH + n) = v0;
            *reinterpret_cast<__half2*>(out + (size_t)(row + 8) * HH + n) = v1;
        }
    }
}

// ---------------------------------------------------------------------------
// Kernel 2: register-resident flash-style attention, log2-domain softmax.
// ---------------------------------------------------------------------------
static constexpr int TST = 72;
static constexpr int TILE_B = 64 * TST * 2;

static constexpr int SM_Q    = 0;
static constexpr int SM_K    = SM_Q + TILE_B;
static constexpr int SM_V    = SM_K + 8 * TILE_B;
static constexpr int SM_MSK  = SM_V + 8 * TILE_B;
static constexpr int SM_WMAX = SM_MSK + SS * 4;
static constexpr int SM_WSUM = SM_WMAX + 4 * 64 * 4;
static constexpr int ATTN_SMEM_TOTAL = SM_WSUM + 4 * 64 * 4;
static constexpr int CTXST = 68;

__global__ __launch_bounds__(512, 1) void attn_kernel(
    const float* __restrict__ mask,
    float* __restrict__ ctx,
    float* __restrict__ probs)
{
    extern __shared__ char smem[];
    const uint32_t smem_base = smem_to_u32(smem);
    float* msk   = (float*)(smem + SM_MSK);
    float* wmax  = (float*)(smem + SM_WMAX);
    float* wsum  = (float*)(smem + SM_WSUM);
    float* ctxb  = (float*)(smem + SM_K);     // aliases K region

    const int qt = blockIdx.x;
    const int h  = blockIdx.y;
    const int b  = blockIdx.z;
    const int tid  = threadIdx.x;
    const int lane = tid & 31;
    const int g    = lane >> 2;
    const int tig  = lane & 3;
    const int mw   = ((tid >> 5) & 3);
    const int nw   = (tid >> 7);
    const int q0 = qt * 64;

    const __half* Q = g_qkvh[0];
    const __half* K = g_qkvh[1];
    const __half* V = g_qkvh[2];

    // mask additive term (log2 domain)
    msk[tid] = (1.0f - mask[(size_t)b * SS + tid]) * MSCALE;

    const int r = tid >> 3, q = tid & 7;

    {
        uint4 v = *reinterpret_cast<const uint4*>(
            Q + ((size_t)(b * SS + q0 + r)) * HH + h * HDD + q * 8);
        *reinterpret_cast<uint4*>((__half*)(smem + SM_Q) + r * TST + q * 8) = v;
    }
    // K commits: tile0, tile1, {2,3}, {4,5}, {6,7}; V -> 1 group
    #pragma unroll
    for (int kt = 0; kt < 8; kt++) {
        CP_ASYNC16(smem_base + SM_K + kt * TILE_B + r * TST * 2 + q * 16,
                   K + ((size_t)(b * SS + kt * 64 + r)) * HH + h * HDD + q * 8);
        if (kt == 0 || kt == 1 || kt == 3 || kt == 5 || kt == 7) CP_COMMIT();
    }
    #pragma unroll
    for (int kt = 0; kt < 8; kt++) {
        CP_ASYNC16(smem_base + SM_V + kt * TILE_B + r * TST * 2 + q * 16,
                   V + ((size_t)(b * SS + kt * 64 + r)) * HH + h * HDD + q * 8);
    }
    CP_COMMIT();

    const uint32_t koff = (nw * 16 + ((lane >> 4) & 1) * 8 + (lane & 7)) * TST * 2
                          + ((lane >> 3) & 1) * 16;
    const uint32_t voff = (nw * 16 + (lane & 7) + ((lane >> 3) & 1) * 8) * TST * 2
                          + ((lane >> 4) & 1) * 16;

    CP_WAIT(5);
    __syncthreads();

    uint32_t qf[4][4];
    {
        const uint32_t qbase = smem_base + SM_Q
            + ((mw * 16 + (lane & 15)) * TST) * 2 + (lane >> 4) * 16;
        #pragma unroll
        for (int kc = 0; kc < 4; kc++)
            LDSM_X4(qf[kc][0], qf[kc][1], qf[kc][2], qf[kc][3], qbase + kc * 32);
    }

    float sreg[8][2][4];
    #pragma unroll
    for (int kt = 0; kt < 8; kt++) {
        if (kt == 1)      { CP_WAIT(4); __syncthreads(); }
        else if (kt == 2) { CP_WAIT(3); __syncthreads(); }
        else if (kt == 4) { CP_WAIT(2); __syncthreads(); }
        else if (kt == 6) { CP_WAIT(1); __syncthreads(); }

        const uint32_t kvb = smem_base + SM_K + kt * TILE_B;
        float acc[2][4];
        #pragma unroll
        for (int ni = 0; ni < 2; ni++)
            #pragma unroll
            for (int rr = 0; rr < 4; rr++) acc[ni][rr] = 0.0f;

        #pragma unroll
        for (int kc = 0; kc < 4; kc++) {
            uint32_t bf[4];
            LDSM_X4(bf[0], bf[1], bf[2], bf[3], kvb + koff + kc * 32);
            mma_fp16(acc[0], qf[kc][0], qf[kc][1], qf[kc][2], qf[kc][3], bf[0], bf[1]);
            mma_fp16(acc[1], qf[kc][0], qf[kc][1], qf[kc][2], qf[kc][3], bf[2], bf[3]);
        }
        // Q was pre-scaled by 0.125*log2e: scores already in log2 domain
        #pragma unroll
        for (int ni = 0; ni < 2; ni++) {
            int col = kt * 64 + nw * 16 + ni * 8 + tig * 2;
            sreg[kt][ni][0] = acc[ni][0] + msk[col];
            sreg[kt][ni][1] = acc[ni][1] + msk[col + 1];
            sreg[kt][ni][2] = acc[ni][2] + msk[col];
            sreg[kt][ni][3] = acc[ni][3] + msk[col + 1];
        }
    }

    const int r0 = mw * 16 + g;
    const int r1 = r0 + 8;

    float m0 = -1e30f, m1 = -1e30f;
    #pragma unroll
    for (int kt = 0; kt < 8; kt++)
        #pragma unroll
        for (int ni = 0; ni < 2; ni++) {
            m0 = fmaxf(m0, fmaxf(sreg[kt][ni][0], sreg[kt][ni][1]));
            m1 = fmaxf(m1, fmaxf(sreg[kt][ni][2], sreg[kt][ni][3]));
        }
    #pragma unroll
    for (int o = 1; o <= 2; o <<= 1) {
        m0 = fmaxf(m0, __shfl_xor_sync(0xffffffffu, m0, o));
        m1 = fmaxf(m1, __shfl_xor_sync(0xffffffffu, m1, o));
    }
    if (tig == 0) {
        wmax[nw * 64 + r0] = m0;
        wmax[nw * 64 + r1] = m1;
    }
    __syncthreads();
    float rm0 = fmaxf(fmaxf(wmax[r0], wmax[64 + r0]), fmaxf(wmax[128 + r0], wmax[192 + r0]));
    float rm1 = fmaxf(fmaxf(wmax[r1], wmax[64 + r1]), fmaxf(wmax[128 + r1], wmax[192 + r1]));

    float s0 = 0.0f, s1 = 0.0f;
    #pragma unroll
    for (int kt = 0; kt < 8; kt++)
        #pragma unroll
        for (int ni = 0; ni < 2; ni++) {
            float e0 = fexp2(sreg[kt][ni][0] - rm0);
            float e1 = fexp2(sreg[kt][ni][1] - rm0);
            float e2 = fexp2(sreg[kt][ni][2] - rm1);
            float e3 = fexp2(sreg[kt][ni][3] - rm1);
            sreg[kt][ni][0] = e0; sreg[kt][ni][1] = e1;
            sreg[kt][ni][2] = e2; sreg[kt][ni][3] = e3;
            s0 += e0 + e1;
            s1 += e2 + e3;
        }
    #pragma unroll
    for (int o = 1; o <= 2; o <<= 1) {
        s0 += __shfl_xor_sync(0xffffffffu, s0, o);
        s1 += __shfl_xor_sync(0xffffffffu, s1, o);
    }
    if (tig == 0) {
        wsum[nw * 64 + r0] = s0;
        wsum[nw * 64 + r1] = s1;
    }
    CP_WAIT(0);
    __syncthreads();
    float inv0 = 1.0f / (wsum[r0] + wsum[64 + r0] + wsum[128 + r0] + wsum[192 + r0]);
    float inv1 = 1.0f / (wsum[r1] + wsum[64 + r1] + wsum[128 + r1] + wsum[192 + r1]);

    const size_t pb0 = (((size_t)b * NHH + h) * SS + q0 + r0) * SS;
    const size_t pb1 = (((size_t)b * NHH + h) * SS + q0 + r1) * SS;

    float cacc[8][4];
    #pragma unroll
    for (int nd = 0; nd < 8; nd++)
        #pragma unroll
        for (int rr = 0; rr < 4; rr++) cacc[nd][rr] = 0.0f;

    #pragma unroll
    for (int kt = 0; kt < 8; kt++) {
        uint32_t paf[4];
        #pragma unroll
        for (int ni = 0; ni < 2; ni++) {
            int col = kt * 64 + nw * 16 + ni * 8 + tig * 2;
            float p0 = sreg[kt][ni][0] * inv0;
            float p1 = sreg[kt][ni][1] * inv0;
            float p2 = sreg[kt][ni][2] * inv1;
            float p3 = sreg[kt][ni][3] * inv1;
            __stcs(reinterpret_cast<float2*>(probs + pb0 + col), make_float2(p0, p1));
            __stcs(reinterpret_cast<float2*>(probs + pb1 + col), make_float2(p2, p3));
            __half2 h01 = __floats2half2_rn(p0, p1);
            __half2 h23 = __floats2half2_rn(p2, p3);
            paf[ni * 2]     = reinterpret_cast<uint32_t&>(h01);
            paf[ni * 2 + 1] = reinterpret_cast<uint32_t&>(h23);
        }
        const uint32_t kvb = smem_base + SM_V + kt * TILE_B;
        #pragma unroll
        for (int dd = 0; dd < 4; dd++) {
            uint32_t bf[4];
            LDSM_X4T(bf[0], bf[1], bf[2], bf[3], kvb + voff + dd * 32);
            mma_fp16(cacc[dd * 2],     paf[0], paf[1], paf[2], paf[3], bf[0], bf[1]);
            mma_fp16(cacc[dd * 2 + 1], paf[0], paf[1], paf[2], paf[3], bf[2], bf[3]);
        }
    }

    #pragma unroll
    for (int nd = 0; nd < 8; nd++) {
        int d = nd * 8 + tig * 2;
        *reinterpret_cast<float2*>(ctxb + (nw * 64 + r0) * CTXST + d) =
            make_float2(cacc[nd][0], cacc[nd][1]);
        *reinterpret_cast<float2*>(ctxb + (nw * 64 + r1) * CTXST + d) =
            make_float2(cacc[nd][2], cacc[nd][3]);
    }
    __syncthreads();

    {
        int row = tid >> 3;
        int d0  = (tid & 7) * 8;
        #pragma unroll
        for (int half = 0; half < 2; half++) {
            int d = d0 + half * 4;
            float4 v0 = *reinterpret_cast<float4*>(ctxb + (0 * 64 + row) * CTXST + d);
            float4 v1 = *reinterpret_cast<float4*>(ctxb + (1 * 64 + row) * CTXST + d);
            float4 v2 = *reinterpret_cast<float4*>(ctxb + (2 * 64 + row) * CTXST + d);
            float4 v3 = *reinterpret_cast<float4*>(ctxb + (3 * 64 + row) * CTXST + d);
            float4 o;
            o.x = v0.x + v1.x + v2.x + v3.x;
            o.y = v0.y + v1.y + v2.y + v3.y;
            o.z = v0.z + v1.z + v2.z + v3.z;
            o.w = v0.w + v1.w + v2.w + v3.w;
            *reinterpret_cast<float4*>(
                ctx + ((size_t)(b * SS + q0 + row)) * HH + h * HDD + d) = o;
        }
    }
}

// ---------------------------------------------------------------------------
// kernel_launch
// ---------------------------------------------------------------------------
extern "C" void kernel_launch(void* const* d_in, const int* in_sizes, int n_in,
                              void* d_out, int out_size)
{
    const float* hidden = (const float*)d_in[0];
    const float* mask   = (const float*)d_in[1];
    const float* Wq = (const float*)d_in[2];
    const float* bq = (const float*)d_in[3];
    const float* Wk = (const float*)d_in[4];
    const float* bk = (const float*)d_in[5];
    const float* Wv = (const float*)d_in[6];
    const float* bv = (const float*)d_in[7];

    float* out   = (float*)d_out;
    float* ctx   = out;
    float* probs = out + (size_t)BB * SS * HH;

    // 0) fp32 -> fp16
    int nblk = (int)((NTOT4 / 4 + 255) / 256);
    split_kernel<<<nblk, 256>>>(hidden, Wq, Wk, Wv);

    // 1) QKV projections (fp16 mma.sync; Q pre-scaled by 0.125*log2e)
    cudaFuncSetAttribute(qkv_gemm_mma, cudaFuncAttributeMaxDynamicSharedMemorySize, GEMM_SMEM_TOTAL);
    dim3 g1(HH / 128, MROWS / 128, 3);
    qkv_gemm_mma<<<g1, 256, GEMM_SMEM_TOTAL>>>(bq, bk, bv);

    // 2) fused attention (log2-domain softmax)
    cudaFuncSetAttribute(attn_kernel, cudaFuncAttributeMaxDynamicSharedMemorySize, ATTN_SMEM_TOTAL);
    dim3 g2(SS / 64, NHH, BB);
    attn_kernel<<<g2, 512, ATTN_SMEM_TOTAL>>>(mask, ctx, probs);
}

// round 16
// speedup vs baseline: 1.1221x; 1.0728x over previous
#include <cuda_runtime.h>
#include <cuda_fp16.h>
#include <cstdint>
#include <math.h>

// Problem constants
static constexpr int BB = 16;     // batch
static constexpr int SS = 512;    // seq len
static constexpr int HH = 768;    // hidden
static constexpr int NHH = 12;    // heads
static constexpr int HDD = 64;    // head dim
static constexpr int MROWS = BB * SS;  // 8192

// Q pre-scale: 1/sqrt(64) * log2(e)  (scores come out in log2 domain)
#define QSCALE 0.1803368801111394f
#define MSCALE (-14426.950408889634f)   // -10000 * log2(e)

// Scratch (static device allocations allowed)
__device__ __half g_qkvh[3][(size_t)MROWS * HH];   // fp16 Q,K,V
__device__ __half g_xh[(size_t)MROWS * HH];        // fp16 hidden
__device__ __half g_wh[3][(size_t)HH * HH];        // fp16 weights

// ---------------------------------------------------------------------------
// helpers
// ---------------------------------------------------------------------------
__device__ __forceinline__ uint32_t smem_to_u32(const void* p) {
    uint32_t a;
    asm("{ .reg .u64 t; cvta.to.shared.u64 t, %1; cvt.u32.u64 %0, t; }" : "=r"(a) : "l"(p));
    return a;
}
#define CP_ASYNC16(dst_u32, src_ptr) \
    asm volatile("cp.async.cg.shared.global [%0], [%1], 16;" :: "r"(dst_u32), "l"(src_ptr) : "memory")
#define CP_COMMIT() asm volatile("cp.async.commit_group;" ::: "memory")
#define CP_WAIT(n)  asm volatile("cp.async.wait_group %0;" :: "n"(n) : "memory")

#define LDSM_X4(r0, r1, r2, r3, a) \
    asm volatile("ldmatrix.sync.aligned.m8n8.x4.shared.b16 {%0,%1,%2,%3}, [%4];" \
                 : "=r"(r0), "=r"(r1), "=r"(r2), "=r"(r3) : "r"(a))
#define LDSM_X4T(r0, r1, r2, r3, a) \
    asm volatile("ldmatrix.sync.aligned.m8n8.x4.trans.shared.b16 {%0,%1,%2,%3}, [%4];" \
                 : "=r"(r0), "=r"(r1), "=r"(r2), "=r"(r3) : "r"(a))

__device__ __forceinline__ void mma_fp16(float d[4],
                                         uint32_t a0, uint32_t a1, uint32_t a2, uint32_t a3,
                                         uint32_t b0, uint32_t b1) {
    asm volatile(
        "mma.sync.aligned.m16n8k16.row.col.f32.f16.f16.f32 "
        "{%0,%1,%2,%3}, {%4,%5,%6,%7}, {%8,%9}, {%0,%1,%2,%3};"
        : "+f"(d[0]), "+f"(d[1]), "+f"(d[2]), "+f"(d[3])
        : "r"(a0), "r"(a1), "r"(a2), "r"(a3), "r"(b0), "r"(b1));
}

// 2^y via MUFU.EX2 (input already in log2 domain; HW underflows to 0)
__device__ __forceinline__ float fexp2(float y) {
    float r;
    asm("ex2.approx.f32 %0, %1;" : "=f"(r) : "f"(y));
    return r;
}

// ---------------------------------------------------------------------------
// Kernel 0: fp32 -> fp16 conversion, 4 independent float4 per thread.
// ---------------------------------------------------------------------------
static constexpr size_t NX4 = (size_t)MROWS * HH / 4;
static constexpr size_t NW4 = (size_t)HH * HH / 4;
static constexpr size_t NTOT4 = NX4 + 3 * NW4;

__device__ __forceinline__ const float* split_src(
    const float* __restrict__ X,
    const float* __restrict__ Wq, const float* __restrict__ Wk, const float* __restrict__ Wv,
    size_t i, __half** dst_out, size_t* off_out)
{
    if (i < NX4) { *dst_out = g_xh; *off_out = i; return X; }
    size_t j = i - NX4;
    int w = (int)(j / NW4);
    *off_out = j - (size_t)w * NW4;
    *dst_out = g_wh[w];
    return (w == 0) ? Wq : (w == 1) ? Wk : Wv;
}

__global__ __launch_bounds__(256) void split_kernel(
    const float* __restrict__ X,
    const float* __restrict__ Wq, const float* __restrict__ Wk, const float* __restrict__ Wv)
{
    const size_t stride = (size_t)gridDim.x * blockDim.x;
    const size_t base = (size_t)blockIdx.x * blockDim.x + threadIdx.x;

    float4 v[4];
    __half* dst[4];
    size_t off[4];
    bool ok[4];

    #pragma unroll
    for (int e = 0; e < 4; e++) {
        size_t i = base + e * stride;
        ok[e] = (i < NTOT4);
        if (ok[e]) {
            const float* src = split_src(X, Wq, Wk, Wv, i, &dst[e], &off[e]);
            v[e] = reinterpret_cast<const float4*>(src)[off[e]];
        }
    }
    #pragma unroll
    for (int e = 0; e < 4; e++) {
        if (ok[e]) {
            __half2 h0 = __floats2half2_rn(v[e].x, v[e].y);
            __half2 h1 = __floats2half2_rn(v[e].z, v[e].w);
            uint2 st;
            st.x = reinterpret_cast<uint32_t&>(h0);
            st.y = reinterpret_cast<uint32_t&>(h1);
            *reinterpret_cast<uint2*>(dst[e] + 4 * off[e]) = st;
        }
    }
}

// ---------------------------------------------------------------------------
// Kernel 1: QKV projection — round-11 proven config; Q epilogue pre-scaled.
// ---------------------------------------------------------------------------
static constexpr int BK = 64;
static constexpr int KSTRIDE = 72;
static constexpr int TILE_BYTES_G = 128 * KSTRIDE * 2;   // 18432
static constexpr int STAGE_BYTES = 2 * TILE_BYTES_G;     // 36864
static constexpr int GEMM_SMEM_TOTAL = 3 * STAGE_BYTES;  // 110592
static constexpr int NKT = HH / BK;                      // 12

__device__ __forceinline__ void load_stage_async(
    char* smem, int s,
    const __half* __restrict__ A, const __half* __restrict__ B,
    int k0, int tid)
{
    char* base = smem + s * STAGE_BYTES;
    #pragma unroll
    for (int e = 0; e < 8; e++) {
        const int tile = e >> 2;
        int idx = ((e & 3) << 8) + tid;
        int r = idx >> 3;
        int q = idx & 7;
        const __half* src = (tile == 0 ? A : B) + (size_t)r * HH + k0 + q * 8;
        uint32_t dst = smem_to_u32(base + tile * TILE_BYTES_G + (r * KSTRIDE + q * 8) * 2);
        CP_ASYNC16(dst, src);
    }
}

__global__ __launch_bounds__(256, 2) void qkv_gemm_mma(
    const float* __restrict__ bq, const float* __restrict__ bk, const float* __restrict__ bv)
{
    extern __shared__ char smem[];
    const uint32_t smem_base = smem_to_u32(smem);
    const int tid = threadIdx.x;
    const int wid = tid >> 5;
    const int lane = tid & 31;
    const int g = lane >> 2;
    const int tig = lane & 3;

    const int which = blockIdx.z;
    const int n0 = blockIdx.x * 128;
    const int m0 = blockIdx.y * 128;
    const float* bias = (which == 0) ? bq : (which == 1) ? bk : bv;
    __half* out = g_qkvh[which];
    const float osc = (which == 0) ? QSCALE : 1.0f;   // pre-scale Q

    const __half* A = g_xh + (size_t)m0 * HH;
    const __half* B = g_wh[which] + (size_t)n0 * HH;

    const int m_w = (wid & 1) * 64;
    const int n_w = (wid >> 1) * 32;

    const uint32_t aoff = ((m_w + (lane & 15)) * KSTRIDE + (lane >> 4) * 8) * 2;
    const uint32_t boff = ((n_w + ((lane >> 4) & 1) * 8 + (lane & 7)) * KSTRIDE
                           + ((lane >> 3) & 1) * 8) * 2;

    float acc[4][4][4];
    #pragma unroll
    for (int i = 0; i < 4; i++)
        #pragma unroll
        for (int j = 0; j < 4; j++)
            #pragma unroll
            for (int r = 0; r < 4; r++) acc[i][j][r] = 0.0f;

    load_stage_async(smem, 0, A, B, 0, tid);
    CP_COMMIT();

    for (int kt = 0; kt < NKT; kt++) {
        const int s = kt % 3;
        if (kt + 1 < NKT) {
            load_stage_async(smem, (kt + 1) % 3, A, B, (kt + 1) * BK, tid);
            CP_COMMIT();
            CP_WAIT(1);
        } else {
            CP_WAIT(0);
        }
        __syncthreads();
        // single barrier per iter (3-stage ring, distance-1 prefetch; no aliasing)

        const uint32_t sA = smem_base + s * STAGE_BYTES;
        const uint32_t sB = sA + TILE_BYTES_G;

        #pragma unroll
        for (int kc = 0; kc < 4; kc++) {
            uint32_t a[4][4];
            #pragma unroll
            for (int mi = 0; mi < 4; mi++)
                LDSM_X4(a[mi][0], a[mi][1], a[mi][2], a[mi][3],
                        sA + aoff + mi * 16 * KSTRIDE * 2 + kc * 32);
            uint32_t b[2][4];
            #pragma unroll
            for (int n2 = 0; n2 < 2; n2++)
                LDSM_X4(b[n2][0], b[n2][1], b[n2][2], b[n2][3],
                        sB + boff + n2 * 16 * KSTRIDE * 2 + kc * 32);
            #pragma unroll
            for (int mi = 0; mi < 4; mi++)
                #pragma unroll
                for (int ni = 0; ni < 4; ni++)
                    mma_fp16(acc[mi][ni], a[mi][0], a[mi][1], a[mi][2], a[mi][3],
                             b[ni >> 1][(ni & 1) * 2], b[ni >> 1][(ni & 1) * 2 + 1]);
        }
    }

    #pragma unroll
    for (int mi = 0; mi < 4; mi++) {
        int row = m0 + m_w + mi * 16 + g;
        #pragma unroll
        for (int ni = 0; ni < 4; ni++) {
            int n = n0 + n_w + ni * 8 + tig * 2;
            float b0f = bias[n] * osc, b1f = bias[n + 1] * osc;
            __half2 v0 = __floats2half2_rn(fmaf(acc[mi][ni][0], osc, b0f),
                                           fmaf(acc[mi][ni][1], osc, b1f));
            __half2 v1 = __floats2half2_rn(fmaf(acc[mi][ni][2], osc, b0f),
                                           fmaf(acc[mi][ni][3], osc, b1f));
            *reinterpret_cast<__half2*>(out + (size_t)row * HH + n) = v0;
            *reinterpret_cast<__half2*>(out + (size_t)(row + 8) * HH + n) = v1;
        }
    }
}

// ---------------------------------------------------------------------------
// Kernel 2: register-resident flash-style attention, log2-domain softmax
// with MUFU.EX2.
// ---------------------------------------------------------------------------
static constexpr int TST = 72;
static constexpr int TILE_B = 64 * TST * 2;

static constexpr int SM_Q    = 0;
static constexpr int SM_K    = SM_Q + TILE_B;
static constexpr int SM_V    = SM_K + 8 * TILE_B;
static constexpr int SM_MSK  = SM_V + 8 * TILE_B;
static constexpr int SM_WMAX = SM_MSK + SS * 4;
static constexpr int SM_WSUM = SM_WMAX + 4 * 64 * 4;
static constexpr int ATTN_SMEM_TOTAL = SM_WSUM + 4 * 64 * 4;
static constexpr int CTXST = 68;

__global__ __launch_bounds__(512, 1) void attn_kernel(
    const float* __restrict__ mask,
    float* __restrict__ ctx,
    float* __restrict__ probs)
{
    extern __shared__ char smem[];
    const uint32_t smem_base = smem_to_u32(smem);
    float* msk   = (float*)(smem + SM_MSK);
    float* wmax  = (float*)(smem + SM_WMAX);
    float* wsum  = (float*)(smem + SM_WSUM);
    float* ctxb  = (float*)(smem + SM_K);     // aliases K region

    const int qt = blockIdx.x;
    const int h  = blockIdx.y;
    const int b  = blockIdx.z;
    const int tid  = threadIdx.x;
    const int lane = tid & 31;
    const int g    = lane >> 2;
    const int tig  = lane & 3;
    const int mw   = ((tid >> 5) & 3);
    const int nw   = (tid >> 7);
    const int q0 = qt * 64;

    const __half* Q = g_qkvh[0];
    const __half* K = g_qkvh[1];
    const __half* V = g_qkvh[2];

    // mask additive term (log2 domain)
    msk[tid] = (1.0f - mask[(size_t)b * SS + tid]) * MSCALE;

    const int r = tid >> 3, q = tid & 7;

    {
        uint4 v = *reinterpret_cast<const uint4*>(
            Q + ((size_t)(b * SS + q0 + r)) * HH + h * HDD + q * 8);
        *reinterpret_cast<uint4*>((__half*)(smem + SM_Q) + r * TST + q * 8) = v;
    }
    // K commits: tile0, tile1, {2,3}, {4,5}, {6,7}; V -> 1 group
    #pragma unroll
    for (int kt = 0; kt < 8; kt++) {
        CP_ASYNC16(smem_base + SM_K + kt * TILE_B + r * TST * 2 + q * 16,
                   K + ((size_t)(b * SS + kt * 64 + r)) * HH + h * HDD + q * 8);
        if (kt == 0 || kt == 1 || kt == 3 || kt == 5 || kt == 7) CP_COMMIT();
    }
    #pragma unroll
    for (int kt = 0; kt < 8; kt++) {
        CP_ASYNC16(smem_base + SM_V + kt * TILE_B + r * TST * 2 + q * 16,
                   V + ((size_t)(b * SS + kt * 64 + r)) * HH + h * HDD + q * 8);
    }
    CP_COMMIT();

    const uint32_t koff = (nw * 16 + ((lane >> 4) & 1) * 8 + (lane & 7)) * TST * 2
                          + ((lane >> 3) & 1) * 16;
    const uint32_t voff = (nw * 16 + (lane & 7) + ((lane >> 3) & 1) * 8) * TST * 2
                          + ((lane >> 4) & 1) * 16;

    CP_WAIT(5);
    __syncthreads();

    uint32_t qf[4][4];
    {
        const uint32_t qbase = smem_base + SM_Q
            + ((mw * 16 + (lane & 15)) * TST) * 2 + (lane >> 4) * 16;
        #pragma unroll
        for (int kc = 0; kc < 4; kc++)
            LDSM_X4(qf[kc][0], qf[kc][1], qf[kc][2], qf[kc][3], qbase + kc * 32);
    }

    float sreg[8][2][4];
    #pragma unroll
    for (int kt = 0; kt < 8; kt++) {
        if (kt == 1)      { CP_WAIT(4); __syncthreads(); }
        else if (kt == 2) { CP_WAIT(3); __syncthreads(); }
        else if (kt == 4) { CP_WAIT(2); __syncthreads(); }
        else if (kt == 6) { CP_WAIT(1); __syncthreads(); }

        const uint32_t kvb = smem_base + SM_K + kt * TILE_B;
        float acc[2][4];
        #pragma unroll
        for (int ni = 0; ni < 2; ni++)
            #pragma unroll
            for (int rr = 0; rr < 4; rr++) acc[ni][rr] = 0.0f;

        #pragma unroll
        for (int kc = 0; kc < 4; kc++) {
            uint32_t bf[4];
            LDSM_X4(bf[0], bf[1], bf[2], bf[3], kvb + koff + kc * 32);
            mma_fp16(acc[0], qf[kc][0], qf[kc][1], qf[kc][2], qf[kc][3], bf[0], bf[1]);
            mma_fp16(acc[1], qf[kc][0], qf[kc][1], qf[kc][2], qf[kc][3], bf[2], bf[3]);
        }
        // Q was pre-scaled by 0.125*log2e: scores already in log2 domain
        #pragma unroll
        for (int ni = 0; ni < 2; ni++) {
            int col = kt * 64 + nw * 16 + ni * 8 + tig * 2;
            sreg[kt][ni][0] = acc[ni][0] + msk[col];
            sreg[kt][ni][1] = acc[ni][1] + msk[col + 1];
            sreg[kt][ni][2] = acc[ni][2] + msk[col];
            sreg[kt][ni][3] = acc[ni][3] + msk[col + 1];
        }
    }

    const int r0 = mw * 16 + g;
    const int r1 = r0 + 8;

    float m0 = -1e30f, m1 = -1e30f;
    #pragma unroll
    for (int kt = 0; kt < 8; kt++)
        #pragma unroll
        for (int ni = 0; ni < 2; ni++) {
            m0 = fmaxf(m0, fmaxf(sreg[kt][ni][0], sreg[kt][ni][1]));
            m1 = fmaxf(m1, fmaxf(sreg[kt][ni][2], sreg[kt][ni][3]));
        }
    #pragma unroll
    for (int o = 1; o <= 2; o <<= 1) {
        m0 = fmaxf(m0, __shfl_xor_sync(0xffffffffu, m0, o));
        m1 = fmaxf(m1, __shfl_xor_sync(0xffffffffu, m1, o));
    }
    if (tig == 0) {
        wmax[nw * 64 + r0] = m0;
        wmax[nw * 64 + r1] = m1;
    }
    __syncthreads();
    float rm0 = fmaxf(fmaxf(wmax[r0], wmax[64 + r0]), fmaxf(wmax[128 + r0], wmax[192 + r0]));
    float rm1 = fmaxf(fmaxf(wmax[r1], wmax[64 + r1]), fmaxf(wmax[128 + r1], wmax[192 + r1]));

    float s0 = 0.0f, s1 = 0.0f;
    #pragma unroll
    for (int kt = 0; kt < 8; kt++)
        #pragma unroll
        for (int ni = 0; ni < 2; ni++) {
            float e0 = fexp2(sreg[kt][ni][0] - rm0);
            float e1 = fexp2(sreg[kt][ni][1] - rm0);
            float e2 = fexp2(sreg[kt][ni][2] - rm1);
            float e3 = fexp2(sreg[kt][ni][3] - rm1);
            sreg[kt][ni][0] = e0; sreg[kt][ni][1] = e1;
            sreg[kt][ni][2] = e2; sreg[kt][ni][3] = e3;
            s0 += e0 + e1;
            s1 += e2 + e3;
        }
    #pragma unroll
    for (int o = 1; o <= 2; o <<= 1) {
        s0 += __shfl_xor_sync(0xffffffffu, s0, o);
        s1 += __shfl_xor_sync(0xffffffffu, s1, o);
    }
    if (tig == 0) {
        wsum[nw * 64 + r0] = s0;
        wsum[nw * 64 + r1] = s1;
    }
    CP_WAIT(0);
    __syncthreads();
    float inv0 = 1.0f / (wsum[r0] + wsum[64 + r0] + wsum[128 + r0] + wsum[192 + r0]);
    float inv1 = 1.0f / (wsum[r1] + wsum[64 + r1] + wsum[128 + r1] + wsum[192 + r1]);

    const size_t pb0 = (((size_t)b * NHH + h) * SS + q0 + r0) * SS;
    const size_t pb1 = (((size_t)b * NHH + h) * SS + q0 + r1) * SS;

    float cacc[8][4];
    #pragma unroll
    for (int nd = 0; nd < 8; nd++)
        #pragma unroll
        for (int rr = 0; rr < 4; rr++) cacc[nd][rr] = 0.0f;

    #pragma unroll
    for (int kt = 0; kt < 8; kt++) {
        uint32_t paf[4];
        #pragma unroll
        for (int ni = 0; ni < 2; ni++) {
            int col = kt * 64 + nw * 16 + ni * 8 + tig * 2;
            float p0 = sreg[kt][ni][0] * inv0;
            float p1 = sreg[kt][ni][1] * inv0;
            float p2 = sreg[kt][ni][2] * inv1;
            float p3 = sreg[kt][ni][3] * inv1;
            __stcs(reinterpret_cast<float2*>(probs + pb0 + col), make_float2(p0, p1));
            __stcs(reinterpret_cast<float2*>(probs + pb1 + col), make_float2(p2, p3));
            __half2 h01 = __floats2half2_rn(p0, p1);
            __half2 h23 = __floats2half2_rn(p2, p3);
            paf[ni * 2]     = reinterpret_cast<uint32_t&>(h01);
            paf[ni * 2 + 1] = reinterpret_cast<uint32_t&>(h23);
        }
        const uint32_t kvb = smem_base + SM_V + kt * TILE_B;
        #pragma unroll
        for (int dd = 0; dd < 4; dd++) {
            uint32_t bf[4];
            LDSM_X4T(bf[0], bf[1], bf[2], bf[3], kvb + voff + dd * 32);
            mma_fp16(cacc[dd * 2],     paf[0], paf[1], paf[2], paf[3], bf[0], bf[1]);
            mma_fp16(cacc[dd * 2 + 1], paf[0], paf[1], paf[2], paf[3], bf[2], bf[3]);
        }
    }

    #pragma unroll
    for (int nd = 0; nd < 8; nd++) {
        int d = nd * 8 + tig * 2;
        *reinterpret_cast<float2*>(ctxb + (nw * 64 + r0) * CTXST + d) =
            make_float2(cacc[nd][0], cacc[nd][1]);
        *reinterpret_cast<float2*>(ctxb + (nw * 64 + r1) * CTXST + d) =
            make_float2(cacc[nd][2], cacc[nd][3]);
    }
    __syncthreads();

    {
        int row = tid >> 3;
        int d0  = (tid & 7) * 8;
        #pragma unroll
        for (int half = 0; half < 2; half++) {
            int d = d0 + half * 4;
            float4 v0 = *reinterpret_cast<float4*>(ctxb + (0 * 64 + row) * CTXST + d);
            float4 v1 = *reinterpret_cast<float4*>(ctxb + (1 * 64 + row) * CTXST + d);
            float4 v2 = *reinterpret_cast<float4*>(ctxb + (2 * 64 + row) * CTXST + d);
            float4 v3 = *reinterpret_cast<float4*>(ctxb + (3 * 64 + row) * CTXST + d);
            float4 o;
            o.x = v0.x + v1.x + v2.x + v3.x;
            o.y = v0.y + v1.y + v2.y + v3.y;
            o.z = v0.z + v1.z + v2.z + v3.z;
            o.w = v0.w + v1.w + v2.w + v3.w;
            *reinterpret_cast<float4*>(
                ctx + ((size_t)(b * SS + q0 + row)) * HH + h * HDD + d) = o;
        }
    }
}

// ---------------------------------------------------------------------------
// kernel_launch
// ---------------------------------------------------------------------------
extern "C" void kernel_launch(void* const* d_in, const int* in_sizes, int n_in,
                              void* d_out, int out_size)
{
    const float* hidden = (const float*)d_in[0];
    const float* mask   = (const float*)d_in[1];
    const float* Wq = (const float*)d_in[2];
    const float* bq = (const float*)d_in[3];
    const float* Wk = (const float*)d_in[4];
    const float* bk = (const float*)d_in[5];
    const float* Wv = (const float*)d_in[6];
    const float* bv = (const float*)d_in[7];

    float* out   = (float*)d_out;
    float* ctx   = out;
    float* probs = out + (size_t)BB * SS * HH;

    // 0) fp32 -> fp16
    int nblk = (int)((NTOT4 / 4 + 255) / 256);
    split_kernel<<<nblk, 256>>>(hidden, Wq, Wk, Wv);

    // 1) QKV projections (fp16 mma.sync; Q pre-scaled by 0.125*log2e)
    cudaFuncSetAttribute(qkv_gemm_mma, cudaFuncAttributeMaxDynamicSharedMemorySize, GEMM_SMEM_TOTAL);
    dim3 g1(HH / 128, MROWS / 128, 3);
    qkv_gemm_mma<<<g1, 256, GEMM_SMEM_TOTAL>>>(bq, bk, bv);

    // 2) fused attention (log2-domain softmax, MUFU.EX2)
    cudaFuncSetAttribute(attn_kernel, cudaFuncAttributeMaxDynamicSharedMemorySize, ATTN_SMEM_TOTAL);
    dim3 g2(SS / 64, NHH, BB);
    attn_kernel<<<g2, 512, ATTN_SMEM_TOTAL>>>(mask, ctx, probs);
}

// round 17
// speedup vs baseline: 1.1225x; 1.0003x over previous
#include <cuda_runtime.h>
#include <cuda_fp16.h>
#include <cstdint>
#include <math.h>

// Problem constants
static constexpr int BB = 16;     // batch
static constexpr int SS = 512;    // seq len
static constexpr int HH = 768;    // hidden
static constexpr int NHH = 12;    // heads
static constexpr int HDD = 64;    // head dim
static constexpr int MROWS = BB * SS;  // 8192

// Q pre-scale: 1/sqrt(64) * log2(e)  (scores come out in log2 domain)
#define QSCALE 0.1803368801111394f
#define MSCALE (-14426.950408889634f)   // -10000 * log2(e)

// Scratch (static device allocations allowed)
__device__ __half g_qkvh[3][(size_t)MROWS * HH];   // fp16 Q,K,V
__device__ __half g_xh[(size_t)MROWS * HH];        // fp16 hidden
__device__ __half g_wh[3][(size_t)HH * HH];        // fp16 weights

// ---------------------------------------------------------------------------
// helpers
// ---------------------------------------------------------------------------
__device__ __forceinline__ uint32_t smem_to_u32(const void* p) {
    uint32_t a;
    asm("{ .reg .u64 t; cvta.to.shared.u64 t, %1; cvt.u32.u64 %0, t; }" : "=r"(a) : "l"(p));
    return a;
}
#define CP_ASYNC16(dst_u32, src_ptr) \
    asm volatile("cp.async.cg.shared.global [%0], [%1], 16;" :: "r"(dst_u32), "l"(src_ptr) : "memory")
#define CP_COMMIT() asm volatile("cp.async.commit_group;" ::: "memory")
#define CP_WAIT(n)  asm volatile("cp.async.wait_group %0;" :: "n"(n) : "memory")

#define LDSM_X4(r0, r1, r2, r3, a) \
    asm volatile("ldmatrix.sync.aligned.m8n8.x4.shared.b16 {%0,%1,%2,%3}, [%4];" \
                 : "=r"(r0), "=r"(r1), "=r"(r2), "=r"(r3) : "r"(a))
#define LDSM_X4T(r0, r1, r2, r3, a) \
    asm volatile("ldmatrix.sync.aligned.m8n8.x4.trans.shared.b16 {%0,%1,%2,%3}, [%4];" \
                 : "=r"(r0), "=r"(r1), "=r"(r2), "=r"(r3) : "r"(a))

__device__ __forceinline__ void mma_fp16(float d[4],
                                         uint32_t a0, uint32_t a1, uint32_t a2, uint32_t a3,
                                         uint32_t b0, uint32_t b1) {
    asm volatile(
        "mma.sync.aligned.m16n8k16.row.col.f32.f16.f16.f32 "
        "{%0,%1,%2,%3}, {%4,%5,%6,%7}, {%8,%9}, {%0,%1,%2,%3};"
        : "+f"(d[0]), "+f"(d[1]), "+f"(d[2]), "+f"(d[3])
        : "r"(a0), "r"(a1), "r"(a2), "r"(a3), "r"(b0), "r"(b1));
}

// 2^y via MUFU.EX2 (input already in log2 domain; HW underflows to 0)
__device__ __forceinline__ float fexp2(float y) {
    float r;
    asm("ex2.approx.f32 %0, %1;" : "=f"(r) : "f"(y));
    return r;
}

// ---------------------------------------------------------------------------
// Kernel 0: fp32 -> fp16 conversion, 6 independent streaming float4 loads per
// thread (read-once data: ldcs evict-first keeps L2 clean for the gemm).
// ---------------------------------------------------------------------------
static constexpr size_t NX4 = (size_t)MROWS * HH / 4;
static constexpr size_t NW4 = (size_t)HH * HH / 4;
static constexpr size_t NTOT4 = NX4 + 3 * NW4;
static constexpr int SPLIT_ELEMS = 6;

__device__ __forceinline__ const float* split_src(
    const float* __restrict__ X,
    const float* __restrict__ Wq, const float* __restrict__ Wk, const float* __restrict__ Wv,
    size_t i, __half** dst_out, size_t* off_out)
{
    if (i < NX4) { *dst_out = g_xh; *off_out = i; return X; }
    size_t j = i - NX4;
    int w = (int)(j / NW4);
    *off_out = j - (size_t)w * NW4;
    *dst_out = g_wh[w];
    return (w == 0) ? Wq : (w == 1) ? Wk : Wv;
}

__global__ __launch_bounds__(256) void split_kernel(
    const float* __restrict__ X,
    const float* __restrict__ Wq, const float* __restrict__ Wk, const float* __restrict__ Wv)
{
    const size_t stride = (size_t)gridDim.x * blockDim.x;
    const size_t base = (size_t)blockIdx.x * blockDim.x + threadIdx.x;

    float4 v[SPLIT_ELEMS];
    __half* dst[SPLIT_ELEMS];
    size_t off[SPLIT_ELEMS];
    bool ok[SPLIT_ELEMS];

    #pragma unroll
    for (int e = 0; e < SPLIT_ELEMS; e++) {
        size_t i = base + (size_t)e * stride;
        ok[e] = (i < NTOT4);
        if (ok[e]) {
            const float* src = split_src(X, Wq, Wk, Wv, i, &dst[e], &off[e]);
            v[e] = __ldcs(reinterpret_cast<const float4*>(src) + off[e]);
        }
    }
    #pragma unroll
    for (int e = 0; e < SPLIT_ELEMS; e++) {
        if (ok[e]) {
            __half2 h0 = __floats2half2_rn(v[e].x, v[e].y);
            __half2 h1 = __floats2half2_rn(v[e].z, v[e].w);
            uint2 st;
            st.x = reinterpret_cast<uint32_t&>(h0);
            st.y = reinterpret_cast<uint32_t&>(h1);
            *reinterpret_cast<uint2*>(dst[e] + 4 * off[e]) = st;
        }
    }
}

// ---------------------------------------------------------------------------
// Kernel 1: QKV projection — round-11 proven config; Q epilogue pre-scaled.
// (byte-identical to the 204.9us round-16 winner)
// ---------------------------------------------------------------------------
static constexpr int BK = 64;
static constexpr int KSTRIDE = 72;
static constexpr int TILE_BYTES_G = 128 * KSTRIDE * 2;   // 18432
static constexpr int STAGE_BYTES = 2 * TILE_BYTES_G;     // 36864
static constexpr int GEMM_SMEM_TOTAL = 3 * STAGE_BYTES;  // 110592
static constexpr int NKT = HH / BK;                      // 12

__device__ __forceinline__ void load_stage_async(
    char* smem, int s,
    const __half* __restrict__ A, const __half* __restrict__ B,
    int k0, int tid)
{
    char* base = smem + s * STAGE_BYTES;
    #pragma unroll
    for (int e = 0; e < 8; e++) {
        const int tile = e >> 2;
        int idx = ((e & 3) << 8) + tid;
        int r = idx >> 3;
        int q = idx & 7;
        const __half* src = (tile == 0 ? A : B) + (size_t)r * HH + k0 + q * 8;
        uint32_t dst = smem_to_u32(base + tile * TILE_BYTES_G + (r * KSTRIDE + q * 8) * 2);
        CP_ASYNC16(dst, src);
    }
}

__global__ __launch_bounds__(256, 2) void qkv_gemm_mma(
    const float* __restrict__ bq, const float* __restrict__ bk, const float* __restrict__ bv)
{
    extern __shared__ char smem[];
    const uint32_t smem_base = smem_to_u32(smem);
    const int tid = threadIdx.x;
    const int wid = tid >> 5;
    const int lane = tid & 31;
    const int g = lane >> 2;
    const int tig = lane & 3;

    const int which = blockIdx.z;
    const int n0 = blockIdx.x * 128;
    const int m0 = blockIdx.y * 128;
    const float* bias = (which == 0) ? bq : (which == 1) ? bk : bv;
    __half* out = g_qkvh[which];
    const float osc = (which == 0) ? QSCALE : 1.0f;   // pre-scale Q

    const __half* A = g_xh + (size_t)m0 * HH;
    const __half* B = g_wh[which] + (size_t)n0 * HH;

    const int m_w = (wid & 1) * 64;
    const int n_w = (wid >> 1) * 32;

    const uint32_t aoff = ((m_w + (lane & 15)) * KSTRIDE + (lane >> 4) * 8) * 2;
    const uint32_t boff = ((n_w + ((lane >> 4) & 1) * 8 + (lane & 7)) * KSTRIDE
                           + ((lane >> 3) & 1) * 8) * 2;

    float acc[4][4][4];
    #pragma unroll
    for (int i = 0; i < 4; i++)
        #pragma unroll
        for (int j = 0; j < 4; j++)
            #pragma unroll
            for (int r = 0; r < 4; r++) acc[i][j][r] = 0.0f;

    load_stage_async(smem, 0, A, B, 0, tid);
    CP_COMMIT();

    for (int kt = 0; kt < NKT; kt++) {
        const int s = kt % 3;
        if (kt + 1 < NKT) {
            load_stage_async(smem, (kt + 1) % 3, A, B, (kt + 1) * BK, tid);
            CP_COMMIT();
            CP_WAIT(1);
        } else {
            CP_WAIT(0);
        }
        __syncthreads();
        // single barrier per iter (3-stage ring, distance-1 prefetch; no aliasing)

        const uint32_t sA = smem_base + s * STAGE_BYTES;
        const uint32_t sB = sA + TILE_BYTES_G;

        #pragma unroll
        for (int kc = 0; kc < 4; kc++) {
            uint32_t a[4][4];
            #pragma unroll
            for (int mi = 0; mi < 4; mi++)
                LDSM_X4(a[mi][0], a[mi][1], a[mi][2], a[mi][3],
                        sA + aoff + mi * 16 * KSTRIDE * 2 + kc * 32);
            uint32_t b[2][4];
            #pragma unroll
            for (int n2 = 0; n2 < 2; n2++)
                LDSM_X4(b[n2][0], b[n2][1], b[n2][2], b[n2][3],
                        sB + boff + n2 * 16 * KSTRIDE * 2 + kc * 32);
            #pragma unroll
            for (int mi = 0; mi < 4; mi++)
                #pragma unroll
                for (int ni = 0; ni < 4; ni++)
                    mma_fp16(acc[mi][ni], a[mi][0], a[mi][1], a[mi][2], a[mi][3],
                             b[ni >> 1][(ni & 1) * 2], b[ni >> 1][(ni & 1) * 2 + 1]);
        }
    }

    #pragma unroll
    for (int mi = 0; mi < 4; mi++) {
        int row = m0 + m_w + mi * 16 + g;
        #pragma unroll
        for (int ni = 0; ni < 4; ni++) {
            int n = n0 + n_w + ni * 8 + tig * 2;
            float b0f = bias[n] * osc, b1f = bias[n + 1] * osc;
            __half2 v0 = __floats2half2_rn(fmaf(acc[mi][ni][0], osc, b0f),
                                           fmaf(acc[mi][ni][1], osc, b1f));
            __half2 v1 = __floats2half2_rn(fmaf(acc[mi][ni][2], osc, b0f),
                                           fmaf(acc[mi][ni][3], osc, b1f));
            *reinterpret_cast<__half2*>(out + (size_t)row * HH + n) = v0;
            *reinterpret_cast<__half2*>(out + (size_t)(row + 8) * HH + n) = v1;
        }
    }
}

// ---------------------------------------------------------------------------
// Kernel 2: register-resident flash-style attention, log2-domain softmax
// with MUFU.EX2. (byte-identical to the 204.9us round-16 winner)
// ---------------------------------------------------------------------------
static constexpr int TST = 72;
static constexpr int TILE_B = 64 * TST * 2;

static constexpr int SM_Q    = 0;
static constexpr int SM_K    = SM_Q + TILE_B;
static constexpr int SM_V    = SM_K + 8 * TILE_B;
static constexpr int SM_MSK  = SM_V + 8 * TILE_B;
static constexpr int SM_WMAX = SM_MSK + SS * 4;
static constexpr int SM_WSUM = SM_WMAX + 4 * 64 * 4;
static constexpr int ATTN_SMEM_TOTAL = SM_WSUM + 4 * 64 * 4;
static constexpr int CTXST = 68;

__global__ __launch_bounds__(512, 1) void attn_kernel(
    const float* __restrict__ mask,
    float* __restrict__ ctx,
    float* __restrict__ probs)
{
    extern __shared__ char smem[];
    const uint32_t smem_base = smem_to_u32(smem);
    float* msk   = (float*)(smem + SM_MSK);
    float* wmax  = (float*)(smem + SM_WMAX);
    float* wsum  = (float*)(smem + SM_WSUM);
    float* ctxb  = (float*)(smem + SM_K);     // aliases K region

    const int qt = blockIdx.x;
    const int h  = blockIdx.y;
    const int b  = blockIdx.z;
    const int tid  = threadIdx.x;
    const int lane = tid & 31;
    const int g    = lane >> 2;
    const int tig  = lane & 3;
    const int mw   = ((tid >> 5) & 3);
    const int nw   = (tid >> 7);
    const int q0 = qt * 64;

    const __half* Q = g_qkvh[0];
    const __half* K = g_qkvh[1];
    const __half* V = g_qkvh[2];

    // mask additive term (log2 domain)
    msk[tid] = (1.0f - mask[(size_t)b * SS + tid]) * MSCALE;

    const int r = tid >> 3, q = tid & 7;

    {
        uint4 v = *reinterpret_cast<const uint4*>(
            Q + ((size_t)(b * SS + q0 + r)) * HH + h * HDD + q * 8);
        *reinterpret_cast<uint4*>((__half*)(smem + SM_Q) + r * TST + q * 8) = v;
    }
    // K commits: tile0, tile1, {2,3}, {4,5}, {6,7}; V -> 1 group
    #pragma unroll
    for (int kt = 0; kt < 8; kt++) {
        CP_ASYNC16(smem_base + SM_K + kt * TILE_B + r * TST * 2 + q * 16,
                   K + ((size_t)(b * SS + kt * 64 + r)) * HH + h * HDD + q * 8);
        if (kt == 0 || kt == 1 || kt == 3 || kt == 5 || kt == 7) CP_COMMIT();
    }
    #pragma unroll
    for (int kt = 0; kt < 8; kt++) {
        CP_ASYNC16(smem_base + SM_V + kt * TILE_B + r * TST * 2 + q * 16,
                   V + ((size_t)(b * SS + kt * 64 + r)) * HH + h * HDD + q * 8);
    }
    CP_COMMIT();

    const uint32_t koff = (nw * 16 + ((lane >> 4) & 1) * 8 + (lane & 7)) * TST * 2
                          + ((lane >> 3) & 1) * 16;
    const uint32_t voff = (nw * 16 + (lane & 7) + ((lane >> 3) & 1) * 8) * TST * 2
                          + ((lane >> 4) & 1) * 16;

    CP_WAIT(5);
    __syncthreads();

    uint32_t qf[4][4];
    {
        const uint32_t qbase = smem_base + SM_Q
            + ((mw * 16 + (lane & 15)) * TST) * 2 + (lane >> 4) * 16;
        #pragma unroll
        for (int kc = 0; kc < 4; kc++)
            LDSM_X4(qf[kc][0], qf[kc][1], qf[kc][2], qf[kc][3], qbase + kc * 32);
    }

    float sreg[8][2][4];
    #pragma unroll
    for (int kt = 0; kt < 8; kt++) {
        if (kt == 1)      { CP_WAIT(4); __syncthreads(); }
        else if (kt == 2) { CP_WAIT(3); __syncthreads(); }
        else if (kt == 4) { CP_WAIT(2); __syncthreads(); }
        else if (kt == 6) { CP_WAIT(1); __syncthreads(); }

        const uint32_t kvb = smem_base + SM_K + kt * TILE_B;
        float acc[2][4];
        #pragma unroll
        for (int ni = 0; ni < 2; ni++)
            #pragma unroll
            for (int rr = 0; rr < 4; rr++) acc[ni][rr] = 0.0f;

        #pragma unroll
        for (int kc = 0; kc < 4; kc++) {
            uint32_t bf[4];
            LDSM_X4(bf[0], bf[1], bf[2], bf[3], kvb + koff + kc * 32);
            mma_fp16(acc[0], qf[kc][0], qf[kc][1], qf[kc][2], qf[kc][3], bf[0], bf[1]);
            mma_fp16(acc[1], qf[kc][0], qf[kc][1], qf[kc][2], qf[kc][3], bf[2], bf[3]);
        }
        // Q was pre-scaled by 0.125*log2e: scores already in log2 domain
        #pragma unroll
        for (int ni = 0; ni < 2; ni++) {
            int col = kt * 64 + nw * 16 + ni * 8 + tig * 2;
            sreg[kt][ni][0] = acc[ni][0] + msk[col];
            sreg[kt][ni][1] = acc[ni][1] + msk[col + 1];
            sreg[kt][ni][2] = acc[ni][2] + msk[col];
            sreg[kt][ni][3] = acc[ni][3] + msk[col + 1];
        }
    }

    const int r0 = mw * 16 + g;
    const int r1 = r0 + 8;

    float m0 = -1e30f, m1 = -1e30f;
    #pragma unroll
    for (int kt = 0; kt < 8; kt++)
        #pragma unroll
        for (int ni = 0; ni < 2; ni++) {
            m0 = fmaxf(m0, fmaxf(sreg[kt][ni][0], sreg[kt][ni][1]));
            m1 = fmaxf(m1, fmaxf(sreg[kt][ni][2], sreg[kt][ni][3]));
        }
    #pragma unroll
    for (int o = 1; o <= 2; o <<= 1) {
        m0 = fmaxf(m0, __shfl_xor_sync(0xffffffffu, m0, o));
        m1 = fmaxf(m1, __shfl_xor_sync(0xffffffffu, m1, o));
    }
    if (tig == 0) {
        wmax[nw * 64 + r0] = m0;
        wmax[nw * 64 + r1] = m1;
    }
    __syncthreads();
    float rm0 = fmaxf(fmaxf(wmax[r0], wmax[64 + r0]), fmaxf(wmax[128 + r0], wmax[192 + r0]));
    float rm1 = fmaxf(fmaxf(wmax[r1], wmax[64 + r1]), fmaxf(wmax[128 + r1], wmax[192 + r1]));

    float s0 = 0.0f, s1 = 0.0f;
    #pragma unroll
    for (int kt = 0; kt < 8; kt++)
        #pragma unroll
        for (int ni = 0; ni < 2; ni++) {
            float e0 = fexp2(sreg[kt][ni][0] - rm0);
            float e1 = fexp2(sreg[kt][ni][1] - rm0);
            float e2 = fexp2(sreg[kt][ni][2] - rm1);
            float e3 = fexp2(sreg[kt][ni][3] - rm1);
            sreg[kt][ni][0] = e0; sreg[kt][ni][1] = e1;
            sreg[kt][ni][2] = e2; sreg[kt][ni][3] = e3;
            s0 += e0 + e1;
            s1 += e2 + e3;
        }
    #pragma unroll
    for (int o = 1; o <= 2; o <<= 1) {
        s0 += __shfl_xor_sync(0xffffffffu, s0, o);
        s1 += __shfl_xor_sync(0xffffffffu, s1, o);
    }
    if (tig == 0) {
        wsum[nw * 64 + r0] = s0;
        wsum[nw * 64 + r1] = s1;
    }
    CP_WAIT(0);
    __syncthreads();
    float inv0 = 1.0f / (wsum[r0] + wsum[64 + r0] + wsum[128 + r0] + wsum[192 + r0]);
    float inv1 = 1.0f / (wsum[r1] + wsum[64 + r1] + wsum[128 + r1] + wsum[192 + r1]);

    const size_t pb0 = (((size_t)b * NHH + h) * SS + q0 + r0) * SS;
    const size_t pb1 = (((size_t)b * NHH + h) * SS + q0 + r1) * SS;

    float cacc[8][4];
    #pragma unroll
    for (int nd = 0; nd < 8; nd++)
        #pragma unroll
        for (int rr = 0; rr < 4; rr++) cacc[nd][rr] = 0.0f;

    #pragma unroll
    for (int kt = 0; kt < 8; kt++) {
        uint32_t paf[4];
        #pragma unroll
        for (int ni = 0; ni < 2; ni++) {
            int col = kt * 64 + nw * 16 + ni * 8 + tig * 2;
            float p0 = sreg[kt][ni][0] * inv0;
            float p1 = sreg[kt][ni][1] * inv0;
            float p2 = sreg[kt][ni][2] * inv1;
            float p3 = sreg[kt][ni][3] * inv1;
            __stcs(reinterpret_cast<float2*>(probs + pb0 + col), make_float2(p0, p1));
            __stcs(reinterpret_cast<float2*>(probs + pb1 + col), make_float2(p2, p3));
            __half2 h01 = __floats2half2_rn(p0, p1);
            __half2 h23 = __floats2half2_rn(p2, p3);
            paf[ni * 2]     = reinterpret_cast<uint32_t&>(h01);
            paf[ni * 2 + 1] = reinterpret_cast<uint32_t&>(h23);
        }
        const uint32_t kvb = smem_base + SM_V + kt * TILE_B;
        #pragma unroll
        for (int dd = 0; dd < 4; dd++) {
            uint32_t bf[4];
            LDSM_X4T(bf[0], bf[1], bf[2], bf[3], kvb + voff + dd * 32);
            mma_fp16(cacc[dd * 2],     paf[0], paf[1], paf[2], paf[3], bf[0], bf[1]);
            mma_fp16(cacc[dd * 2 + 1], paf[0], paf[1], paf[2], paf[3], bf[2], bf[3]);
        }
    }

    #pragma unroll
    for (int nd = 0; nd < 8; nd++) {
        int d = nd * 8 + tig * 2;
        *reinterpret_cast<float2*>(ctxb + (nw * 64 + r0) * CTXST + d) =
            make_float2(cacc[nd][0], cacc[nd][1]);
        *reinterpret_cast<float2*>(ctxb + (nw * 64 + r1) * CTXST + d) =
            make_float2(cacc[nd][2], cacc[nd][3]);
    }
    __syncthreads();

    {
        int row = tid >> 3;
        int d0  = (tid & 7) * 8;
        #pragma unroll
        for (int half = 0; half < 2; half++) {
            int d = d0 + half * 4;
            float4 v0 = *reinterpret_cast<float4*>(ctxb + (0 * 64 + row) * CTXST + d);
            float4 v1 = *reinterpret_cast<float4*>(ctxb + (1 * 64 + row) * CTXST + d);
            float4 v2 = *reinterpret_cast<float4*>(ctxb + (2 * 64 + row) * CTXST + d);
            float4 v3 = *reinterpret_cast<float4*>(ctxb + (3 * 64 + row) * CTXST + d);
            float4 o;
            o.x = v0.x + v1.x + v2.x + v3.x;
            o.y = v0.y + v1.y + v2.y + v3.y;
            o.z = v0.z + v1.z + v2.z + v3.z;
            o.w = v0.w + v1.w + v2.w + v3.w;
            *reinterpret_cast<float4*>(
                ctx + ((size_t)(b * SS + q0 + row)) * HH + h * HDD + d) = o;
        }
    }
}

// ---------------------------------------------------------------------------
// kernel_launch
// ---------------------------------------------------------------------------
extern "C" void kernel_launch(void* const* d_in, const int* in_sizes, int n_in,
                              void* d_out, int out_size)
{
    const float* hidden = (const float*)d_in[0];
    const float* mask   = (const float*)d_in[1];
    const float* Wq = (const float*)d_in[2];
    const float* bq = (const float*)d_in[3];
    const float* Wk = (const float*)d_in[4];
    const float* bk = (const float*)d_in[5];
    const float* Wv = (const float*)d_in[6];
    const float* bv = (const float*)d_in[7];

    float* out   = (float*)d_out;
    float* ctx   = out;
    float* probs = out + (size_t)BB * SS * HH;

    // 0) fp32 -> fp16 (6 streaming float4 per thread)
    int nblk = (int)((NTOT4 / SPLIT_ELEMS + 255) / 256);
    split_kernel<<<nblk, 256>>>(hidden, Wq, Wk, Wv);

    // 1) QKV projections (fp16 mma.sync; Q pre-scaled by 0.125*log2e)
    cudaFuncSetAttribute(qkv_gemm_mma, cudaFuncAttributeMaxDynamicSharedMemorySize, GEMM_SMEM_TOTAL);
    dim3 g1(HH / 128, MROWS / 128, 3);
    qkv_gemm_mma<<<g1, 256, GEMM_SMEM_TOTAL>>>(bq, bk, bv);

    // 2) fused attention (log2-domain softmax, MUFU.EX2)
    cudaFuncSetAttribute(attn_kernel, cudaFuncAttributeMaxDynamicSharedMemorySize, ATTN_SMEM_TOTAL);
    dim3 g2(SS / 64, NHH, BB);
    attn_kernel<<<g2, 512, ATTN_SMEM_TOTAL>>>(mask, ctx, probs);
}